// round 2
// baseline (speedup 1.0000x reference)
#include <cuda_runtime.h>

// Problem constants
#define B_  256
#define O_  128
#define H_  1024
#define HH  512
#define I_  2048
#define DFF 1536

// ---------------- device scratch (no allocation allowed) ----------------
__device__ __align__(16) float g_hW[B_ * HH];          // h @ W_e^T + b_e   (256x512)
__device__ __align__(16) float g_partial[B_ * O_ * 4]; // score partials (4 col-blocks)
__device__ __align__(16) float g_phi[B_ * HH];         // attention-pooled phi (256x512)
__device__ __align__(16) float g_z[B_ * 4096];         // [phi | X_F | h | c] (256x4096)
__device__ __align__(16) float g_gates[B_ * 4096];     // gate preactivations (256x[4x1024])
__device__ int g_mflag;                                // 0=bool bytes, 1=float32, 2=int32

typedef unsigned long long u64;

// ---------------- packed f32x2 helpers (FFMA2, sm_100+) ----------------
__device__ __forceinline__ u64 pack2(float lo, float hi) {
    u64 r; asm("mov.b64 %0, {%1,%2};" : "=l"(r) : "f"(lo), "f"(hi)); return r;
}
__device__ __forceinline__ void fma2(u64& d, u64 a, u64 b) {
    asm("fma.rn.f32x2 %0, %1, %2, %0;" : "+l"(d) : "l"(a), "l"(b));
}
__device__ __forceinline__ void unpack2(u64 v, float& l, float& h) {
    asm("mov.b64 {%0,%1}, %2;" : "=f"(l), "=f"(h) : "l"(v));
}
__device__ __forceinline__ float sigmoidf_(float x) { return 1.0f / (1.0f + expf(-x)); }

// ---------------- kernel 0: sniff x_mask dtype ----------------
// bool: bytes in {0,1} at every offset. int32 0/1: nonzero bytes only at
// offset%4==0. float32: 1.0f contains bytes 0x80,0x3F (>=2).
__global__ void k_sniff(const unsigned char* __restrict__ m) {
    __shared__ int anyBig, off123;
    if (threadIdx.x == 0) { anyBig = 0; off123 = 0; }
    __syncthreads();
    int big = 0, o123 = 0;
    for (int i = threadIdx.x; i < 4096; i += blockDim.x) {
        unsigned char v = m[i];
        if (v >= 2) big = 1;
        if ((i & 3) != 0 && v != 0) o123 = 1;
    }
    if (big) atomicOr(&anyBig, 1);
    if (o123) atomicOr(&off123, 1);
    __syncthreads();
    if (threadIdx.x == 0) {
        g_mflag = anyBig ? 1 : (off123 ? 0 : 2);
    }
}

// ---------------- kernel 1: g_hW = h @ W_e^T + b_e  (256x512, K=1024) ----------------
// NT GEMM, 64x64 tile, 256 threads, 4x4 micro-tile (as 4x2 f32x2 pairs).
__global__ void __launch_bounds__(256, 2)
k_hW(const float* __restrict__ h, const float* __restrict__ We,
     const float* __restrict__ be) {
    __shared__ __align__(16) float As[2][8][64];
    __shared__ __align__(16) float Bs[2][8][64];
    int t = threadIdx.x;
    int m0 = blockIdx.y * 64, n0 = blockIdx.x * 64;
    int tx = t & 15, ty = t >> 4;
    int lr = t >> 1, lp = (t & 1) * 4;
    const float* Ap = h  + (m0 + lr) * H_ + lp;
    const float* Bp = We + (n0 + lr) * H_ + lp;

    u64 acc[4][2] = {};
    float4 a4 = make_float4(0,0,0,0), b4 = make_float4(0,0,0,0);
    if (t < 128) { a4 = *(const float4*)Ap; b4 = *(const float4*)Bp; }
    if (t < 128) {
        As[0][lp+0][lr]=a4.x; As[0][lp+1][lr]=a4.y; As[0][lp+2][lr]=a4.z; As[0][lp+3][lr]=a4.w;
        Bs[0][lp+0][lr]=b4.x; Bs[0][lp+1][lr]=b4.y; Bs[0][lp+2][lr]=b4.z; Bs[0][lp+3][lr]=b4.w;
    }
    __syncthreads();
    int buf = 0;
    const int KT = H_ / 8;
    for (int kt = 0; kt < KT; kt++) {
        if (kt < KT - 1 && t < 128) {
            a4 = *(const float4*)(Ap + (kt + 1) * 8);
            b4 = *(const float4*)(Bp + (kt + 1) * 8);
        }
#pragma unroll
        for (int kk = 0; kk < 8; kk++) {
            float4 av = *(const float4*)&As[buf][kk][ty * 4];
            u64 b0 = *(const u64*)&Bs[buf][kk][tx * 4];
            u64 b1 = *(const u64*)&Bs[buf][kk][tx * 4 + 2];
            u64 ap;
            ap = pack2(av.x, av.x); fma2(acc[0][0], ap, b0); fma2(acc[0][1], ap, b1);
            ap = pack2(av.y, av.y); fma2(acc[1][0], ap, b0); fma2(acc[1][1], ap, b1);
            ap = pack2(av.z, av.z); fma2(acc[2][0], ap, b0); fma2(acc[2][1], ap, b1);
            ap = pack2(av.w, av.w); fma2(acc[3][0], ap, b0); fma2(acc[3][1], ap, b1);
        }
        if (kt < KT - 1) {
            int nb = buf ^ 1;
            if (t < 128) {
                As[nb][lp+0][lr]=a4.x; As[nb][lp+1][lr]=a4.y; As[nb][lp+2][lr]=a4.z; As[nb][lp+3][lr]=a4.w;
                Bs[nb][lp+0][lr]=b4.x; Bs[nb][lp+1][lr]=b4.y; Bs[nb][lp+2][lr]=b4.z; Bs[nb][lp+3][lr]=b4.w;
            }
            buf = nb;
        }
        __syncthreads();
    }
#pragma unroll
    for (int i = 0; i < 4; i++) {
        int row = m0 + ty * 4 + i;
#pragma unroll
        for (int jp = 0; jp < 2; jp++) {
            float l, hv; unpack2(acc[i][jp], l, hv);
            int c0 = n0 + tx * 4 + jp * 2;
            g_hW[row * HH + c0]     = l  + be[c0];
            g_hW[row * HH + c0 + 1] = hv + be[c0 + 1];
        }
    }
}

// ---------------- kernel 2: attention scores (the 17.2 GF GEMM, fused epilogue) ----
// Per block: one b, all 128 o-rows, 128 of the 512 U_e columns.
// score_partial[b,o,cb] = sum_{n in colblock} tanh(x_j[b,o]·U_e[n] + hW[b,n]) * w[n]
__global__ void __launch_bounds__(256, 1)
k_scores(const float* __restrict__ xj, const float* __restrict__ Ue,
         const float* __restrict__ w) {
    __shared__ __align__(16) float As[2][8][128];
    __shared__ __align__(16) float Bs[2][8][128];
    __shared__ float hWs[128], ws[128];
    int b = blockIdx.y, n0 = blockIdx.x * 128;
    int t = threadIdx.x, tx = t & 15, ty = t >> 4;
    int lr = t >> 1, lp = (t & 1) * 4;
    const float* Ap = xj + (b * O_ + lr) * HH + lp;
    const float* Bp = Ue + (n0 + lr) * HH + lp;
    if (t < 128) { hWs[t] = g_hW[b * HH + n0 + t]; ws[t] = w[n0 + t]; }

    u64 acc[8][4] = {};
    float4 a4 = *(const float4*)Ap;
    float4 b4 = *(const float4*)Bp;
    As[0][lp+0][lr]=a4.x; As[0][lp+1][lr]=a4.y; As[0][lp+2][lr]=a4.z; As[0][lp+3][lr]=a4.w;
    Bs[0][lp+0][lr]=b4.x; Bs[0][lp+1][lr]=b4.y; Bs[0][lp+2][lr]=b4.z; Bs[0][lp+3][lr]=b4.w;
    __syncthreads();
    int buf = 0;
    for (int kt = 0; kt < 64; kt++) {
        if (kt < 63) {
            a4 = *(const float4*)(Ap + (kt + 1) * 8);
            b4 = *(const float4*)(Bp + (kt + 1) * 8);
        }
#pragma unroll
        for (int kk = 0; kk < 8; kk++) {
            float4 al = *(const float4*)&As[buf][kk][ty * 8];
            float4 ah = *(const float4*)&As[buf][kk][ty * 8 + 4];
            u64 bb0 = *(const u64*)&Bs[buf][kk][tx * 8];
            u64 bb1 = *(const u64*)&Bs[buf][kk][tx * 8 + 2];
            u64 bb2 = *(const u64*)&Bs[buf][kk][tx * 8 + 4];
            u64 bb3 = *(const u64*)&Bs[buf][kk][tx * 8 + 6];
            float av[8] = {al.x, al.y, al.z, al.w, ah.x, ah.y, ah.z, ah.w};
#pragma unroll
            for (int i = 0; i < 8; i++) {
                u64 ap = pack2(av[i], av[i]);
                fma2(acc[i][0], ap, bb0); fma2(acc[i][1], ap, bb1);
                fma2(acc[i][2], ap, bb2); fma2(acc[i][3], ap, bb3);
            }
        }
        if (kt < 63) {
            int nb = buf ^ 1;
            As[nb][lp+0][lr]=a4.x; As[nb][lp+1][lr]=a4.y; As[nb][lp+2][lr]=a4.z; As[nb][lp+3][lr]=a4.w;
            Bs[nb][lp+0][lr]=b4.x; Bs[nb][lp+1][lr]=b4.y; Bs[nb][lp+2][lr]=b4.z; Bs[nb][lp+3][lr]=b4.w;
            buf = nb;
        }
        __syncthreads();
    }
    // fused epilogue: tanh -> *w -> reduce over the 128 columns of this block
    float rowsum[8];
#pragma unroll
    for (int i = 0; i < 8; i++) {
        float s = 0.f;
#pragma unroll
        for (int jp = 0; jp < 4; jp++) {
            float l, hv; unpack2(acc[i][jp], l, hv);
            int cc = tx * 8 + jp * 2;
            s += tanhf(l  + hWs[cc])     * ws[cc];
            s += tanhf(hv + hWs[cc + 1]) * ws[cc + 1];
        }
        rowsum[i] = s;
    }
#pragma unroll
    for (int off = 8; off >= 1; off >>= 1)
#pragma unroll
        for (int i = 0; i < 8; i++)
            rowsum[i] += __shfl_xor_sync(0xffffffffu, rowsum[i], off, 16);
    if (tx == 0) {
#pragma unroll
        for (int i = 0; i < 8; i++)
            g_partial[(b * O_ + ty * 8 + i) * 4 + blockIdx.x] = rowsum[i];
    }
}

// ---------------- kernel 3: mask + softmax + phi  (one block per b) ----------------
__global__ void k_softmax_phi(const void* __restrict__ mask, const float* __restrict__ xj) {
    __shared__ float sa[128];
    __shared__ float red[128];
    int b = blockIdx.x, t = threadIdx.x;  // 128 threads
    int mf = g_mflag;
    const float* pr = g_partial + (b * O_ + t) * 4;
    float s = pr[0] + pr[1] + pr[2] + pr[3];
    bool mv;
    int mi = b * O_ + t;
    if (mf == 1)      mv = ((const float*)mask)[mi] != 0.0f;
    else if (mf == 2) mv = ((const int*)mask)[mi] != 0;
    else              mv = ((const unsigned char*)mask)[mi] != 0;
    if (!mv) s = -1e9f;

    red[t] = s; __syncthreads();
    for (int off = 64; off > 0; off >>= 1) {
        if (t < off) red[t] = fmaxf(red[t], red[t + off]);
        __syncthreads();
    }
    float mx = red[0]; __syncthreads();
    float e = expf(s - mx);
    red[t] = e; __syncthreads();
    for (int off = 64; off > 0; off >>= 1) {
        if (t < off) red[t] += red[t + off];
        __syncthreads();
    }
    float denom = red[0];
    sa[t] = e / denom;
    __syncthreads();

    // phi[b, :] = sum_o a[o] * x_j[b,o,:]; thread t owns float4 column chunk t
    float4 accv = make_float4(0, 0, 0, 0);
    const float4* xr = (const float4*)(xj + (size_t)b * O_ * HH) + t;  // row stride 128 float4
    for (int o = 0; o < O_; o++) {
        float a = sa[o];
        float4 v = xr[o * 128];
        accv.x += a * v.x; accv.y += a * v.y; accv.z += a * v.z; accv.w += a * v.w;
    }
    ((float4*)g_phi)[b * 128 + t] = accv;
}

// ---------------- kernel 3b: gather z = [phi | X_F | h | c] ----------------
__global__ void k_gather(const float* __restrict__ XF, const float* __restrict__ h,
                         const float* __restrict__ c) {
    int b = blockIdx.x, t = threadIdx.x;  // 1024 threads, one float4 each
    float4 v;
    if (t < 128)       v = ((const float4*)(g_phi + b * HH))[t];
    else if (t < 512)  v = ((const float4*)(XF + b * DFF))[t - 128];
    else if (t < 768)  v = ((const float4*)(h + b * H_))[t - 512];
    else               v = ((const float4*)(c + b * H_))[t - 768];
    ((float4*)(g_z + b * 4096))[t] = v;
}

// ---------------- kernel 4: fused gate GEMM (256 x 4096, virtual K=4096) -------------
// Virtual B matrix per output col n (gate g=n>>10, j=n&1023):
//   kk<2048 -> W_g[j,kk]; kk<3072 -> U_g[j,kk-2048]; else V_g[j,kk-3072] (zero for g==2)
__global__ void __launch_bounds__(256, 1)
k_gates(const float* __restrict__ Wi, const float* __restrict__ Wf,
        const float* __restrict__ Wc, const float* __restrict__ Wo,
        const float* __restrict__ Ui, const float* __restrict__ Uf,
        const float* __restrict__ Uc, const float* __restrict__ Uo,
        const float* __restrict__ Vi, const float* __restrict__ Vf,
        const float* __restrict__ Vo) {
    __shared__ __align__(16) float As[2][8][64];
    __shared__ __align__(16) float Bs[2][8][128];
    int t = threadIdx.x, tx = t & 15, ty = t >> 4;
    int n0 = blockIdx.x * 128, m0 = blockIdx.y * 64;
    int g = n0 >> 10;
    const float* Wg = (g == 0) ? Wi : (g == 1) ? Wf : (g == 2) ? Wc : Wo;
    const float* Ug = (g == 0) ? Ui : (g == 1) ? Uf : (g == 2) ? Uc : Uo;
    const float* Vg = (g == 0) ? Vi : (g == 1) ? Vf : (g == 3) ? Vo : nullptr;
    int jb = n0 & 1023;
    int lr = t >> 1, lp = (t & 1) * 4;
    const float* Ap = g_z + (m0 + lr) * 4096 + lp;  // valid only for t<128
    int bcol = jb + lr;

    u64 acc[4][4] = {};
    float4 a4 = make_float4(0,0,0,0), b4;

    auto loadB = [&](int k0) -> float4 {
        int kp = k0 + lp;
        if (k0 < 2048)      return *(const float4*)(Wg + bcol * 2048 + kp);
        else if (k0 < 3072) return *(const float4*)(Ug + bcol * 1024 + (kp - 2048));
        else if (Vg)        return *(const float4*)(Vg + bcol * 1024 + (kp - 3072));
        else                return make_float4(0, 0, 0, 0);
    };

    if (t < 128) a4 = *(const float4*)Ap;
    b4 = loadB(0);
    if (t < 128) {
        As[0][lp+0][lr]=a4.x; As[0][lp+1][lr]=a4.y; As[0][lp+2][lr]=a4.z; As[0][lp+3][lr]=a4.w;
    }
    Bs[0][lp+0][lr]=b4.x; Bs[0][lp+1][lr]=b4.y; Bs[0][lp+2][lr]=b4.z; Bs[0][lp+3][lr]=b4.w;
    __syncthreads();
    int buf = 0;
    const int KT = 4096 / 8;
    for (int kt = 0; kt < KT; kt++) {
        if (kt < KT - 1) {
            if (t < 128) a4 = *(const float4*)(Ap + (kt + 1) * 8);
            b4 = loadB((kt + 1) * 8);
        }
#pragma unroll
        for (int kk = 0; kk < 8; kk++) {
            float4 av = *(const float4*)&As[buf][kk][ty * 4];
            u64 bb0 = *(const u64*)&Bs[buf][kk][tx * 8];
            u64 bb1 = *(const u64*)&Bs[buf][kk][tx * 8 + 2];
            u64 bb2 = *(const u64*)&Bs[buf][kk][tx * 8 + 4];
            u64 bb3 = *(const u64*)&Bs[buf][kk][tx * 8 + 6];
            u64 ap;
            ap = pack2(av.x, av.x); fma2(acc[0][0],ap,bb0); fma2(acc[0][1],ap,bb1); fma2(acc[0][2],ap,bb2); fma2(acc[0][3],ap,bb3);
            ap = pack2(av.y, av.y); fma2(acc[1][0],ap,bb0); fma2(acc[1][1],ap,bb1); fma2(acc[1][2],ap,bb2); fma2(acc[1][3],ap,bb3);
            ap = pack2(av.z, av.z); fma2(acc[2][0],ap,bb0); fma2(acc[2][1],ap,bb1); fma2(acc[2][2],ap,bb2); fma2(acc[2][3],ap,bb3);
            ap = pack2(av.w, av.w); fma2(acc[3][0],ap,bb0); fma2(acc[3][1],ap,bb1); fma2(acc[3][2],ap,bb2); fma2(acc[3][3],ap,bb3);
        }
        if (kt < KT - 1) {
            int nb = buf ^ 1;
            if (t < 128) {
                As[nb][lp+0][lr]=a4.x; As[nb][lp+1][lr]=a4.y; As[nb][lp+2][lr]=a4.z; As[nb][lp+3][lr]=a4.w;
            }
            Bs[nb][lp+0][lr]=b4.x; Bs[nb][lp+1][lr]=b4.y; Bs[nb][lp+2][lr]=b4.z; Bs[nb][lp+3][lr]=b4.w;
            buf = nb;
        }
        __syncthreads();
    }
#pragma unroll
    for (int i = 0; i < 4; i++) {
        int row = m0 + ty * 4 + i;
#pragma unroll
        for (int jp = 0; jp < 4; jp++) {
            float l, hv; unpack2(acc[i][jp], l, hv);
            int cn = n0 + tx * 8 + jp * 2;
            g_gates[row * 4096 + cn]     = l;
            g_gates[row * 4096 + cn + 1] = hv;
        }
    }
}

// ---------------- kernel 5: elementwise LSTM update ----------------
__global__ void k_final(const float* __restrict__ c,
                        const float* __restrict__ bi, const float* __restrict__ bf,
                        const float* __restrict__ bc, const float* __restrict__ bo,
                        float* __restrict__ out) {
    int idx = blockIdx.x * 256 + threadIdx.x;  // < 262144
    int b = idx >> 10, j = idx & 1023;
    const float* gr = g_gates + b * 4096;
    float gi = gr[j]        + bi[j];
    float gf = gr[1024 + j] + bf[j];
    float gc = gr[2048 + j] + bc[j];
    float go = gr[3072 + j] + bo[j];
    float si = sigmoidf_(gi);
    float sf = sigmoidf_(gf);
    float so = sigmoidf_(go);
    float cold = c[idx];
    float nc = sf * cold + si * tanhf(gc);
    float nh = so * tanhf(nc);
    out[idx] = nh;                 // new_h
    out[B_ * H_ + idx] = nc;       // new_c
}

// ---------------- launch ----------------
extern "C" void kernel_launch(void* const* d_in, const int* in_sizes, int n_in,
                              void* d_out, int out_size) {
    const float* x_j  = (const float*)d_in[0];
    const void*  mask = d_in[1];
    const float* X_F  = (const float*)d_in[2];
    const float* h    = (const float*)d_in[3];
    const float* c    = (const float*)d_in[4];
    const float* W_i  = (const float*)d_in[5];
    const float* W_f  = (const float*)d_in[6];
    const float* W_c  = (const float*)d_in[7];
    const float* W_o  = (const float*)d_in[8];
    const float* U_i  = (const float*)d_in[9];
    const float* U_f  = (const float*)d_in[10];
    const float* U_c  = (const float*)d_in[11];
    const float* U_o  = (const float*)d_in[12];
    const float* V_i  = (const float*)d_in[13];
    const float* V_f  = (const float*)d_in[14];
    const float* V_o  = (const float*)d_in[16];
    const float* b_i  = (const float*)d_in[17];
    const float* b_f  = (const float*)d_in[18];
    const float* b_c  = (const float*)d_in[19];
    const float* b_o  = (const float*)d_in[20];
    const float* w    = (const float*)d_in[21];
    const float* W_e  = (const float*)d_in[22];
    const float* U_e  = (const float*)d_in[23];
    const float* b_e  = (const float*)d_in[24];

    k_sniff<<<1, 256>>>((const unsigned char*)mask);
    k_hW<<<dim3(8, 4), 256>>>(h, W_e, b_e);
    k_scores<<<dim3(4, 256), 256>>>(x_j, U_e, w);
    k_softmax_phi<<<256, 128>>>(mask, x_j);
    k_gather<<<256, 1024>>>(X_F, h, c);
    k_gates<<<dim3(32, 4), 256>>>(W_i, W_f, W_c, W_o,
                                  U_i, U_f, U_c, U_o,
                                  V_i, V_f, V_o);
    k_final<<<1024, 256>>>(c, b_i, b_f, b_c, b_o, (float*)d_out);
}

// round 6
// speedup vs baseline: 2.9263x; 2.9263x over previous
#include <cuda_runtime.h>
#include <cuda_bf16.h>
#include <cstdint>

// Problem constants
#define B_  256
#define O_  128
#define H_  1024
#define HH  512
#define I_  2048
#define DFF 1536

typedef unsigned long long u64;

// ---------------- device scratch ----------------
__device__ __align__(16) float g_hW[B_ * HH];        // h@W_e^T + b_e
__device__ __align__(16) float g_partial[B_ * O_ * 4];
__device__ __align__(16) float g_attn[B_ * O_];
__device__ __align__(16) float g_phi[B_ * HH];
__device__ __align__(16) float g_z[B_ * 4096];       // [phi|X_F|h|c]
__device__ __align__(16) float g_gp[2 * B_ * 4096];  // split-K gate partials
__device__ int g_mflag;

// ---------------- helpers ----------------
__device__ __forceinline__ uint32_t smem_u32(const void* p) {
    uint32_t a;
    asm("{ .reg .u64 t; cvta.to.shared.u64 t, %1; cvt.u32.u64 %0, t; }" : "=r"(a) : "l"(p));
    return a;
}
__device__ __forceinline__ uint32_t swz(uint32_t off) { return off ^ ((off >> 3) & 0x70); }

__device__ __forceinline__ void ldsm4(uint32_t* r, uint32_t addr) {
    asm volatile("ldmatrix.sync.aligned.m8n8.x4.shared.b16 {%0,%1,%2,%3},[%4];"
        : "=r"(r[0]), "=r"(r[1]), "=r"(r[2]), "=r"(r[3]) : "r"(addr));
}
__device__ __forceinline__ void mma16816(float* c, const uint32_t* a, const uint32_t* b) {
    asm volatile("mma.sync.aligned.m16n8k16.row.col.f32.bf16.bf16.f32 "
        "{%0,%1,%2,%3},{%4,%5,%6,%7},{%8,%9},{%0,%1,%2,%3};"
        : "+f"(c[0]), "+f"(c[1]), "+f"(c[2]), "+f"(c[3])
        : "r"(a[0]), "r"(a[1]), "r"(a[2]), "r"(a[3]), "r"(b[0]), "r"(b[1]));
}

// split f32 -> (hi bf16 trunc, lo bf16 rn) pairs, stored swizzled as u64
__device__ __forceinline__ void cvt_store(char* hib, char* lob, uint32_t off, float4 v) {
    uint32_t so = swz(off);
    uint32_t hx = __float_as_uint(v.x), hy = __float_as_uint(v.y);
    uint32_t hz = __float_as_uint(v.z), hw = __float_as_uint(v.w);
    uint32_t hp0 = __byte_perm(hx, hy, 0x7632);
    uint32_t hp1 = __byte_perm(hz, hw, 0x7632);
    float lx = v.x - __uint_as_float(hx & 0xffff0000u);
    float ly = v.y - __uint_as_float(hy & 0xffff0000u);
    float lz = v.z - __uint_as_float(hz & 0xffff0000u);
    float lw = v.w - __uint_as_float(hw & 0xffff0000u);
    __nv_bfloat162 lp0 = __floats2bfloat162_rn(lx, ly);
    __nv_bfloat162 lp1 = __floats2bfloat162_rn(lz, lw);
    uint32_t l0, l1;
    memcpy(&l0, &lp0, 4); memcpy(&l1, &lp1, 4);
    *(u64*)(hib + so) = (u64)hp0 | ((u64)hp1 << 32);
    *(u64*)(lob + so) = (u64)l0  | ((u64)l1  << 32);
}

__device__ __forceinline__ float sigmoidf_(float x) { return 1.0f / (1.0f + expf(-x)); }

// ---------------- kernel 0: sniff mask dtype ----------------
__global__ void k_sniff(const unsigned char* __restrict__ m) {
    __shared__ int anyBig, off123;
    if (threadIdx.x == 0) { anyBig = 0; off123 = 0; }
    __syncthreads();
    int big = 0, o123 = 0;
    for (int i = threadIdx.x; i < 4096; i += blockDim.x) {
        unsigned char v = m[i];
        if (v >= 2) big = 1;
        if ((i & 3) != 0 && v != 0) o123 = 1;
    }
    if (big) atomicOr(&anyBig, 1);
    if (o123) atomicOr(&off123, 1);
    __syncthreads();
    if (threadIdx.x == 0) g_mflag = anyBig ? 1 : (off123 ? 0 : 2);
}

// ---------------- kernel 1: g_hW = h @ W_e^T + b_e (FFMA2, small) ----------------
__global__ void __launch_bounds__(256, 2)
k_hW(const float* __restrict__ h, const float* __restrict__ We,
     const float* __restrict__ be) {
    __shared__ __align__(16) float As[2][8][64];
    __shared__ __align__(16) float Bs[2][8][64];
    int t = threadIdx.x;
    int m0 = blockIdx.y * 64, n0 = blockIdx.x * 64;
    int tx = t & 15, ty = t >> 4;
    int lr = t >> 1, lp = (t & 1) * 4;
    const float* Ap = h  + (m0 + lr) * H_ + lp;
    const float* Bp = We + (n0 + lr) * H_ + lp;

    u64 acc[4][2] = {};
    float4 a4 = make_float4(0,0,0,0), b4 = make_float4(0,0,0,0);
    if (t < 128) { a4 = *(const float4*)Ap; b4 = *(const float4*)Bp; }
    if (t < 128) {
        As[0][lp+0][lr]=a4.x; As[0][lp+1][lr]=a4.y; As[0][lp+2][lr]=a4.z; As[0][lp+3][lr]=a4.w;
        Bs[0][lp+0][lr]=b4.x; Bs[0][lp+1][lr]=b4.y; Bs[0][lp+2][lr]=b4.z; Bs[0][lp+3][lr]=b4.w;
    }
    __syncthreads();
    int buf = 0;
    const int KT = H_ / 8;
    for (int kt = 0; kt < KT; kt++) {
        if (kt < KT - 1 && t < 128) {
            a4 = *(const float4*)(Ap + (kt + 1) * 8);
            b4 = *(const float4*)(Bp + (kt + 1) * 8);
        }
#pragma unroll
        for (int kk = 0; kk < 8; kk++) {
            float4 av = *(const float4*)&As[buf][kk][ty * 4];
            u64 b0 = *(const u64*)&Bs[buf][kk][tx * 4];
            u64 b1 = *(const u64*)&Bs[buf][kk][tx * 4 + 2];
            u64 ap;
            asm("mov.b64 %0,{%1,%1};" : "=l"(ap) : "f"(av.x));
            asm("fma.rn.f32x2 %0,%1,%2,%0;" : "+l"(acc[0][0]) : "l"(ap), "l"(b0));
            asm("fma.rn.f32x2 %0,%1,%2,%0;" : "+l"(acc[0][1]) : "l"(ap), "l"(b1));
            asm("mov.b64 %0,{%1,%1};" : "=l"(ap) : "f"(av.y));
            asm("fma.rn.f32x2 %0,%1,%2,%0;" : "+l"(acc[1][0]) : "l"(ap), "l"(b0));
            asm("fma.rn.f32x2 %0,%1,%2,%0;" : "+l"(acc[1][1]) : "l"(ap), "l"(b1));
            asm("mov.b64 %0,{%1,%1};" : "=l"(ap) : "f"(av.z));
            asm("fma.rn.f32x2 %0,%1,%2,%0;" : "+l"(acc[2][0]) : "l"(ap), "l"(b0));
            asm("fma.rn.f32x2 %0,%1,%2,%0;" : "+l"(acc[2][1]) : "l"(ap), "l"(b1));
            asm("mov.b64 %0,{%1,%1};" : "=l"(ap) : "f"(av.w));
            asm("fma.rn.f32x2 %0,%1,%2,%0;" : "+l"(acc[3][0]) : "l"(ap), "l"(b0));
            asm("fma.rn.f32x2 %0,%1,%2,%0;" : "+l"(acc[3][1]) : "l"(ap), "l"(b1));
        }
        if (kt < KT - 1) {
            int nb = buf ^ 1;
            if (t < 128) {
                As[nb][lp+0][lr]=a4.x; As[nb][lp+1][lr]=a4.y; As[nb][lp+2][lr]=a4.z; As[nb][lp+3][lr]=a4.w;
                Bs[nb][lp+0][lr]=b4.x; Bs[nb][lp+1][lr]=b4.y; Bs[nb][lp+2][lr]=b4.z; Bs[nb][lp+3][lr]=b4.w;
            }
            buf = nb;
        }
        __syncthreads();
    }
#pragma unroll
    for (int i = 0; i < 4; i++) {
        int row = m0 + ty * 4 + i;
#pragma unroll
        for (int jp = 0; jp < 2; jp++) {
            float l, hv;
            asm("mov.b64 {%0,%1},%2;" : "=f"(l), "=f"(hv) : "l"(acc[i][jp]));
            int c0 = n0 + tx * 4 + jp * 2;
            g_hW[row * HH + c0]     = l  + be[c0];
            g_hW[row * HH + c0 + 1] = hv + be[c0 + 1];
        }
    }
}

// ================== shared mma-GEMM core constants ==================
// buffer: AH(0) AL(16K) BH(32K) BL(48K); BUFSZ=64K; double buffered
#define BUFSZ 65536u
#define A_LO  16384u
#define B_HI  32768u
#define B_LO  49152u

// mma over one 64-wide k-chunk: acc[2][8][4] += split-bf16 3-term
__device__ __forceinline__ void mma_chunk(float acc[2][8][4], uint32_t bb,
                                          int wm, int wn, int lane) {
#pragma unroll
    for (int ks = 0; ks < 4; ks++) {
        uint32_t bh[4][4], bl[4][4];
        int mm = lane >> 3, ch = mm & 1;
        int rhalf = ((mm >> 1) << 3) + (lane & 7);
#pragma unroll
        for (int p = 0; p < 4; p++) {
            uint32_t off = (uint32_t)(wn * 64 + p * 16 + rhalf) * 128 + ks * 32 + ch * 16;
            uint32_t so = swz(off);
            ldsm4(bh[p], bb + B_HI + so);
            ldsm4(bl[p], bb + B_LO + so);
        }
#pragma unroll
        for (int mt = 0; mt < 2; mt++) {
            uint32_t offa = (uint32_t)(wm * 32 + mt * 16 + (lane & 15)) * 128
                          + ks * 32 + (lane >> 4) * 16;
            uint32_t soa = swz(offa);
            uint32_t ah[4], al[4];
            ldsm4(ah, bb + soa);
#pragma unroll
            for (int nt = 0; nt < 8; nt++)
                mma16816(acc[mt][nt], ah, &bh[nt >> 1][(nt & 1) * 2]);
#pragma unroll
            for (int nt = 0; nt < 8; nt++)
                mma16816(acc[mt][nt], ah, &bl[nt >> 1][(nt & 1) * 2]);
            ldsm4(al, bb + A_LO + soa);
#pragma unroll
            for (int nt = 0; nt < 8; nt++)
                mma16816(acc[mt][nt], al, &bh[nt >> 1][(nt & 1) * 2]);
        }
    }
}

// ---------------- kernel 2: scores GEMM (mma.sync, split-bf16) ----------------
// grid (4, 256): nq = n-quarter (128 cols of U_e), b = batch. M = 128 objects.
__global__ void __launch_bounds__(256, 1)
k_scores_mma(const float* __restrict__ xj, const float* __restrict__ Ue,
             const float* __restrict__ w) {
    extern __shared__ __align__(1024) char smem[];
    uint32_t S = smem_u32(smem);
    const int t = threadIdx.x, wid = t >> 5, lane = t & 31;
    const int wm = wid >> 1, wn = wid & 1;
    const int nq = blockIdx.x, b = blockIdx.y;
    const int n0 = nq * 128;

    const uint32_t OFF_HW = 0, OFF_W = 512, OFF_RS = 1024, OFF_BUF = 2048;
    float* hWs = (float*)(smem + OFF_HW);
    float* ws  = (float*)(smem + OFF_W);
    float* rs  = (float*)(smem + OFF_RS);

    if (t < 128) { hWs[t] = g_hW[b * HH + n0 + t]; ws[t] = w[n0 + t]; }

    const float4* Ag = (const float4*)xj + (size_t)b * O_ * 128;
    const float4* Bg = (const float4*)Ue + (size_t)n0 * 128;

    float4 pa[8], pb[8];
    auto loadAB = [&](int kc) {
#pragma unroll
        for (int i = 0; i < 8; i++) {
            int idx = i * 256 + t, row = idx >> 4, f4 = idx & 15;
            pa[i] = Ag[row * 128 + kc * 16 + f4];
            pb[i] = Bg[row * 128 + kc * 16 + f4];
        }
    };
    auto storeAB = [&](int buf) {
        char* base = smem + OFF_BUF + buf * BUFSZ;
#pragma unroll
        for (int i = 0; i < 8; i++) {
            int idx = i * 256 + t, row = idx >> 4, f4 = idx & 15;
            uint32_t off = (uint32_t)row * 128 + f4 * 8;
            cvt_store(base, base + A_LO, off, pa[i]);
            cvt_store(base + B_HI, base + B_LO, off, pb[i]);
        }
    };

    float acc[2][8][4] = {};
    loadAB(0);
    storeAB(0);
    __syncthreads();
    for (int c = 0; c < 8; c++) {
        if (c + 1 < 8) loadAB(c + 1);
        mma_chunk(acc, S + OFF_BUF + (c & 1) * BUFSZ, wm, wn, lane);
        if (c + 1 < 8) { storeAB((c + 1) & 1); __syncthreads(); }
    }

    // epilogue: tanh(C + hW) * w, reduce over 128 cols
    int g = lane >> 2, q = lane & 3;
#pragma unroll
    for (int mt = 0; mt < 2; mt++) {
        float sA = 0.f, sB = 0.f;
#pragma unroll
        for (int nt = 0; nt < 8; nt++) {
            int col = wn * 64 + nt * 8 + q * 2;
            sA += tanhf(acc[mt][nt][0] + hWs[col])     * ws[col];
            sA += tanhf(acc[mt][nt][1] + hWs[col + 1]) * ws[col + 1];
            sB += tanhf(acc[mt][nt][2] + hWs[col])     * ws[col];
            sB += tanhf(acc[mt][nt][3] + hWs[col + 1]) * ws[col + 1];
        }
        sA += __shfl_xor_sync(0xffffffffu, sA, 1);
        sA += __shfl_xor_sync(0xffffffffu, sA, 2);
        sB += __shfl_xor_sync(0xffffffffu, sB, 1);
        sB += __shfl_xor_sync(0xffffffffu, sB, 2);
        if (q == 0) {
            int r0 = wm * 32 + mt * 16 + g;
            rs[wn * 128 + r0]     = sA;
            rs[wn * 128 + r0 + 8] = sB;
        }
    }
    __syncthreads();
    if (t < 128)
        g_partial[(b * O_ + t) * 4 + nq] = rs[t] + rs[128 + t];
}

// ---------------- kernel 3: softmax ----------------
__global__ void k_softmax(const void* __restrict__ mask) {
    __shared__ float red[128];
    int b = blockIdx.x, t = threadIdx.x;  // 128 threads
    int mf = g_mflag;
    const float* pr = g_partial + (b * O_ + t) * 4;
    float s = pr[0] + pr[1] + pr[2] + pr[3];
    bool mv;
    int mi = b * O_ + t;
    if (mf == 1)      mv = ((const float*)mask)[mi] != 0.0f;
    else if (mf == 2) mv = ((const int*)mask)[mi] != 0;
    else              mv = ((const unsigned char*)mask)[mi] != 0;
    if (!mv) s = -1e9f;

    red[t] = s; __syncthreads();
    for (int off = 64; off > 0; off >>= 1) {
        if (t < off) red[t] = fmaxf(red[t], red[t + off]);
        __syncthreads();
    }
    float mx = red[0]; __syncthreads();
    float e = expf(s - mx);
    red[t] = e; __syncthreads();
    for (int off = 64; off > 0; off >>= 1) {
        if (t < off) red[t] += red[t + off];
        __syncthreads();
    }
    g_attn[b * O_ + t] = e / red[0];
}

// ---------------- kernel 3b: phi = a^T x_j  (grid 256x4) ----------------
__global__ void k_phi(const float* __restrict__ xj) {
    __shared__ float av[128];
    __shared__ float4 part[4][32];
    int b = blockIdx.x, cb = blockIdx.y, t = threadIdx.x;  // 128 threads
    av[t] = g_attn[b * O_ + t];
    __syncthreads();
    int col = cb * 32 + (t & 31);
    int og = t >> 5;
    const float4* X = (const float4*)xj + (size_t)b * O_ * 128;
    float4 acc = make_float4(0, 0, 0, 0);
    for (int o = og * 32; o < og * 32 + 32; o++) {
        float a = av[o];
        float4 v = X[(size_t)o * 128 + col];
        acc.x += a * v.x; acc.y += a * v.y; acc.z += a * v.z; acc.w += a * v.w;
    }
    part[og][t & 31] = acc;
    __syncthreads();
    if (t < 32) {
        float4 r = part[0][t], p1 = part[1][t], p2 = part[2][t], p3 = part[3][t];
        r.x += p1.x + p2.x + p3.x; r.y += p1.y + p2.y + p3.y;
        r.z += p1.z + p2.z + p3.z; r.w += p1.w + p2.w + p3.w;
        ((float4*)g_phi)[b * 128 + cb * 32 + t] = r;
    }
}

// ---------------- kernel 3c: gather z = [phi | X_F | h | c] ----------------
__global__ void k_gather(const float* __restrict__ XF, const float* __restrict__ h,
                         const float* __restrict__ c) {
    int b = blockIdx.x, t = threadIdx.x;  // 1024 threads, one float4 each
    float4 v;
    if (t < 128)       v = ((const float4*)(g_phi + b * HH))[t];
    else if (t < 512)  v = ((const float4*)(XF + (size_t)b * DFF))[t - 128];
    else if (t < 768)  v = ((const float4*)(h + (size_t)b * H_))[t - 512];
    else               v = ((const float4*)(c + (size_t)b * H_))[t - 768];
    ((float4*)(g_z + (size_t)b * 4096))[t] = v;
}

// ---------------- kernel 4: gates GEMM (mma.sync, split-bf16, split-K=2) -------------
// grid (32, 2, 2): bx = n-block(128), by = m-block(128), bz = K split
__global__ void __launch_bounds__(256, 1)
k_gates_mma(const float* __restrict__ Wi, const float* __restrict__ Wf,
            const float* __restrict__ Wc, const float* __restrict__ Wo,
            const float* __restrict__ Ui, const float* __restrict__ Uf,
            const float* __restrict__ Uc, const float* __restrict__ Uo,
            const float* __restrict__ Vi, const float* __restrict__ Vf,
            const float* __restrict__ Vo) {
    extern __shared__ __align__(1024) char smem[];
    uint32_t S = smem_u32(smem);
    const int t = threadIdx.x, wid = t >> 5, lane = t & 31;
    const int wm = wid >> 1, wn = wid & 1;
    const int nb_ = blockIdx.x, mb = blockIdx.y, ksp = blockIdx.z;
    const int n0g = nb_ * 128;
    const int gg = n0g >> 10;
    const int jb = n0g & 1023;
    const float* Wg = (gg == 0) ? Wi : (gg == 1) ? Wf : (gg == 2) ? Wc : Wo;
    const float* Ug = (gg == 0) ? Ui : (gg == 1) ? Uf : (gg == 2) ? Uc : Uo;
    const float* Vg = (gg == 0) ? Vi : (gg == 1) ? Vf : (gg == 3) ? Vo : nullptr;

    const float4* Ag = (const float4*)g_z + (size_t)mb * 128 * 1024;

    float4 pa[8], pb[8];
    auto loadAB = [&](int kc) {
        int kk0 = ksp * 2048 + kc * 64;
#pragma unroll
        for (int i = 0; i < 8; i++) {
            int idx = i * 256 + t, row = idx >> 4, f4 = idx & 15;
            pa[i] = Ag[(size_t)row * 1024 + (kk0 >> 2) + f4];
        }
        const float* bp = nullptr; int rstride = 0; bool zer = false;
        if (kk0 < 2048)      { bp = Wg + kk0;          rstride = 2048; }
        else if (kk0 < 3072) { bp = Ug + (kk0 - 2048); rstride = 1024; }
        else if (Vg)         { bp = Vg + (kk0 - 3072); rstride = 1024; }
        else                 { zer = true; }
#pragma unroll
        for (int i = 0; i < 8; i++) {
            int idx = i * 256 + t, row = idx >> 4, f4 = idx & 15;
            pb[i] = zer ? make_float4(0, 0, 0, 0)
                        : *(const float4*)(bp + (size_t)(jb + row) * rstride + f4 * 4);
        }
    };
    auto storeAB = [&](int buf) {
        char* base = smem + buf * BUFSZ;
#pragma unroll
        for (int i = 0; i < 8; i++) {
            int idx = i * 256 + t, row = idx >> 4, f4 = idx & 15;
            uint32_t off = (uint32_t)row * 128 + f4 * 8;
            cvt_store(base, base + A_LO, off, pa[i]);
            cvt_store(base + B_HI, base + B_LO, off, pb[i]);
        }
    };

    float acc[2][8][4] = {};
    loadAB(0);
    storeAB(0);
    __syncthreads();
    for (int c = 0; c < 32; c++) {
        if (c + 1 < 32) loadAB(c + 1);
        mma_chunk(acc, S + (c & 1) * BUFSZ, wm, wn, lane);
        if (c + 1 < 32) { storeAB((c + 1) & 1); __syncthreads(); }
    }

    // epilogue: store fp32 partials
    int g = lane >> 2, q = lane & 3;
#pragma unroll
    for (int mt = 0; mt < 2; mt++) {
        int m = mb * 128 + wm * 32 + mt * 16 + g;
        float* baseA = g_gp + (size_t)(ksp * B_ + m) * 4096 + n0g;
        float* baseB = g_gp + (size_t)(ksp * B_ + m + 8) * 4096 + n0g;
#pragma unroll
        for (int nt = 0; nt < 8; nt++) {
            int col = wn * 64 + nt * 8 + q * 2;
            *(float2*)(baseA + col) = make_float2(acc[mt][nt][0], acc[mt][nt][1]);
            *(float2*)(baseB + col) = make_float2(acc[mt][nt][2], acc[mt][nt][3]);
        }
    }
}

// ---------------- kernel 5: elementwise LSTM update ----------------
__global__ void k_final(const float* __restrict__ c,
                        const float* __restrict__ bi, const float* __restrict__ bf,
                        const float* __restrict__ bc, const float* __restrict__ bo,
                        float* __restrict__ out) {
    int idx = blockIdx.x * 256 + threadIdx.x;
    int b = idx >> 10, j = idx & 1023;
    const float* gA = g_gp + (size_t)b * 4096;
    const float* gB = g_gp + (size_t)(B_ + b) * 4096;
    float gi = gA[j]        + gB[j]        + bi[j];
    float gf = gA[1024 + j] + gB[1024 + j] + bf[j];
    float gc = gA[2048 + j] + gB[2048 + j] + bc[j];
    float go = gA[3072 + j] + gB[3072 + j] + bo[j];
    float si = sigmoidf_(gi);
    float sf = sigmoidf_(gf);
    float so = sigmoidf_(go);
    float cold = c[idx];
    float nc = sf * cold + si * tanhf(gc);
    float nh = so * tanhf(nc);
    out[idx] = nh;
    out[B_ * H_ + idx] = nc;
}

// ---------------- launch ----------------
extern "C" void kernel_launch(void* const* d_in, const int* in_sizes, int n_in,
                              void* d_out, int out_size) {
    const float* x_j  = (const float*)d_in[0];
    const void*  mask = d_in[1];
    const float* X_F  = (const float*)d_in[2];
    const float* h    = (const float*)d_in[3];
    const float* c    = (const float*)d_in[4];
    const float* W_i  = (const float*)d_in[5];
    const float* W_f  = (const float*)d_in[6];
    const float* W_c  = (const float*)d_in[7];
    const float* W_o  = (const float*)d_in[8];
    const float* U_i  = (const float*)d_in[9];
    const float* U_f  = (const float*)d_in[10];
    const float* U_c  = (const float*)d_in[11];
    const float* U_o  = (const float*)d_in[12];
    const float* V_i  = (const float*)d_in[13];
    const float* V_f  = (const float*)d_in[14];
    const float* V_o  = (const float*)d_in[16];
    const float* b_i  = (const float*)d_in[17];
    const float* b_f  = (const float*)d_in[18];
    const float* b_c  = (const float*)d_in[19];
    const float* b_o  = (const float*)d_in[20];
    const float* w    = (const float*)d_in[21];
    const float* W_e  = (const float*)d_in[22];
    const float* U_e  = (const float*)d_in[23];
    const float* b_e  = (const float*)d_in[24];

    cudaFuncSetAttribute(k_scores_mma, cudaFuncAttributeMaxDynamicSharedMemorySize, 133120);
    cudaFuncSetAttribute(k_gates_mma,  cudaFuncAttributeMaxDynamicSharedMemorySize, 131072);

    k_sniff<<<1, 256>>>((const unsigned char*)mask);
    k_hW<<<dim3(8, 4), 256>>>(h, W_e, b_e);
    k_scores_mma<<<dim3(4, 256), 256, 133120>>>(x_j, U_e, w);
    k_softmax<<<256, 128>>>(mask);
    k_phi<<<dim3(256, 4), 128>>>(x_j);
    k_gather<<<256, 1024>>>(X_F, h, c);
    k_gates_mma<<<dim3(32, 2, 2), 256, 131072>>>(W_i, W_f, W_c, W_o,
                                                 U_i, U_f, U_c, U_o,
                                                 V_i, V_f, V_o);
    k_final<<<1024, 256>>>(c, b_i, b_f, b_c, b_o, (float*)d_out);
}

// round 10
// speedup vs baseline: 3.2323x; 1.1046x over previous
#include <cuda_runtime.h>
#include <cuda_fp16.h>
#include <cstdint>

// Problem constants
#define B_  256
#define O_  128
#define H_  1024
#define HH  512
#define I_  2048
#define DFF 1536

typedef unsigned long long u64;

// ---------------- device scratch ----------------
__device__ __align__(16) float g_hW[B_ * HH];          // h@W_e^T + b_e
__device__ __align__(16) float g_partial[B_ * O_ * 4]; // score partials
__device__ __align__(16) __half g_xjh[B_ * O_ * HH];   // x_j in fp16 (32MB)
__device__ __align__(16) __half g_UeH[HH * HH];        // U_e fp16 hi
__device__ __align__(16) __half g_UeL[HH * HH];        // U_e fp16 residual
__device__ __align__(16) __half g_zh[B_ * 4096];       // [phi|X_F|h|c] fp16
__device__ __align__(16) float g_gp[2 * B_ * 4096];    // split-K gate partials
__device__ int g_mflag;

// ---------------- helpers ----------------
__device__ __forceinline__ uint32_t smem_u32(const void* p) {
    uint32_t a;
    asm("{ .reg .u64 t; cvta.to.shared.u64 t, %1; cvt.u32.u64 %0, t; }" : "=r"(a) : "l"(p));
    return a;
}
__device__ __forceinline__ uint32_t swz(uint32_t off) { return off ^ ((off >> 3) & 0x70); }

__device__ __forceinline__ void ldsm4(uint32_t* r, uint32_t addr) {
    asm volatile("ldmatrix.sync.aligned.m8n8.x4.shared.b16 {%0,%1,%2,%3},[%4];"
        : "=r"(r[0]), "=r"(r[1]), "=r"(r[2]), "=r"(r[3]) : "r"(addr));
}
__device__ __forceinline__ void mma16816(float* c, const uint32_t* a, const uint32_t* b) {
    asm volatile("mma.sync.aligned.m16n8k16.row.col.f32.f16.f16.f32 "
        "{%0,%1,%2,%3},{%4,%5,%6,%7},{%8,%9},{%0,%1,%2,%3};"
        : "+f"(c[0]), "+f"(c[1]), "+f"(c[2]), "+f"(c[3])
        : "r"(a[0]), "r"(a[1]), "r"(a[2]), "r"(a[3]), "r"(b[0]), "r"(b[1]));
}
__device__ __forceinline__ void cp16(uint32_t dst, const void* src) {
    asm volatile("cp.async.cg.shared.global [%0],[%1],16;" :: "r"(dst), "l"(src));
}
#define CP_COMMIT() asm volatile("cp.async.commit_group;" ::: "memory")
#define CP_WAIT0()  asm volatile("cp.async.wait_group 0;" ::: "memory")

__device__ __forceinline__ uint32_t pk2(float a, float b) {
    __half2 x = __floats2half2_rn(a, b);
    uint32_t r; memcpy(&r, &x, 4); return r;
}
__device__ __forceinline__ float sigmoidf_(float x) { return 1.0f / (1.0f + expf(-x)); }

// fp16 hi/lo split of a float4, stored swizzled as u64 each
__device__ __forceinline__ void cvt_f16split(char* hib, char* lob, uint32_t off, float4 v) {
    uint32_t so = swz(off);
    __half2 h0 = __floats2half2_rn(v.x, v.y);
    __half2 h1 = __floats2half2_rn(v.z, v.w);
    float2 f0 = __half22float2(h0), f1 = __half22float2(h1);
    uint32_t l0 = pk2(v.x - f0.x, v.y - f0.y);
    uint32_t l1 = pk2(v.z - f1.x, v.w - f1.y);
    uint32_t hh0, hh1; memcpy(&hh0, &h0, 4); memcpy(&hh1, &h1, 4);
    *(u64*)(hib + so) = (u64)hh0 | ((u64)hh1 << 32);
    *(u64*)(lob + so) = (u64)l0  | ((u64)l1  << 32);
}

// ---------------- kernel 0: sniff mask dtype ----------------
__global__ void k_sniff(const unsigned char* __restrict__ m) {
    __shared__ int anyBig, off123;
    if (threadIdx.x == 0) { anyBig = 0; off123 = 0; }
    __syncthreads();
    int big = 0, o123 = 0;
    for (int i = threadIdx.x; i < 4096; i += blockDim.x) {
        unsigned char v = m[i];
        if (v >= 2) big = 1;
        if ((i & 3) != 0 && v != 0) o123 = 1;
    }
    if (big) atomicOr(&anyBig, 1);
    if (o123) atomicOr(&off123, 1);
    __syncthreads();
    if (threadIdx.x == 0) g_mflag = anyBig ? 1 : (off123 ? 0 : 2);
}

// ---------------- conversion kernels ----------------
__global__ void k_cvt_xj(const float* __restrict__ xj) {
    size_t i = ((size_t)blockIdx.x * 256 + threadIdx.x) * 8;
    float4 v0 = *(const float4*)(xj + i);
    float4 v1 = *(const float4*)(xj + i + 4);
    uint4 o;
    o.x = pk2(v0.x, v0.y); o.y = pk2(v0.z, v0.w);
    o.z = pk2(v1.x, v1.y); o.w = pk2(v1.z, v1.w);
    *(uint4*)(g_xjh + i) = o;
}
__global__ void k_cvt_ue(const float* __restrict__ Ue) {
    size_t i = ((size_t)blockIdx.x * 256 + threadIdx.x) * 8;
    float4 v0 = *(const float4*)(Ue + i);
    float4 v1 = *(const float4*)(Ue + i + 4);
    __half2 h0 = __floats2half2_rn(v0.x, v0.y), h1 = __floats2half2_rn(v0.z, v0.w);
    __half2 h2 = __floats2half2_rn(v1.x, v1.y), h3 = __floats2half2_rn(v1.z, v1.w);
    float2 f0 = __half22float2(h0), f1 = __half22float2(h1);
    float2 f2 = __half22float2(h2), f3 = __half22float2(h3);
    uint4 hi, lo;
    memcpy(&hi.x, &h0, 4); memcpy(&hi.y, &h1, 4); memcpy(&hi.z, &h2, 4); memcpy(&hi.w, &h3, 4);
    lo.x = pk2(v0.x - f0.x, v0.y - f0.y); lo.y = pk2(v0.z - f1.x, v0.w - f1.y);
    lo.z = pk2(v1.x - f2.x, v1.y - f2.y); lo.w = pk2(v1.z - f3.x, v1.w - f3.y);
    *(uint4*)(g_UeH + i) = hi;
    *(uint4*)(g_UeL + i) = lo;
}

// ---------------- kernel 1: g_hW = h @ W_e^T + b_e (FFMA2, small) ----------------
__global__ void __launch_bounds__(256, 2)
k_hW(const float* __restrict__ h, const float* __restrict__ We,
     const float* __restrict__ be) {
    __shared__ __align__(16) float As[2][8][64];
    __shared__ __align__(16) float Bs[2][8][64];
    int t = threadIdx.x;
    int m0 = blockIdx.y * 64, n0 = blockIdx.x * 64;
    int tx = t & 15, ty = t >> 4;
    int lr = t >> 1, lp = (t & 1) * 4;
    const float* Ap = h  + (m0 + lr) * H_ + lp;
    const float* Bp = We + (n0 + lr) * H_ + lp;

    u64 acc[4][2] = {};
    float4 a4 = make_float4(0,0,0,0), b4 = make_float4(0,0,0,0);
    if (t < 128) { a4 = *(const float4*)Ap; b4 = *(const float4*)Bp; }
    if (t < 128) {
        As[0][lp+0][lr]=a4.x; As[0][lp+1][lr]=a4.y; As[0][lp+2][lr]=a4.z; As[0][lp+3][lr]=a4.w;
        Bs[0][lp+0][lr]=b4.x; Bs[0][lp+1][lr]=b4.y; Bs[0][lp+2][lr]=b4.z; Bs[0][lp+3][lr]=b4.w;
    }
    __syncthreads();
    int buf = 0;
    const int KT = H_ / 8;
    for (int kt = 0; kt < KT; kt++) {
        if (kt < KT - 1 && t < 128) {
            a4 = *(const float4*)(Ap + (kt + 1) * 8);
            b4 = *(const float4*)(Bp + (kt + 1) * 8);
        }
#pragma unroll
        for (int kk = 0; kk < 8; kk++) {
            float4 av = *(const float4*)&As[buf][kk][ty * 4];
            u64 b0 = *(const u64*)&Bs[buf][kk][tx * 4];
            u64 b1 = *(const u64*)&Bs[buf][kk][tx * 4 + 2];
            u64 ap;
            asm("mov.b64 %0,{%1,%1};" : "=l"(ap) : "f"(av.x));
            asm("fma.rn.f32x2 %0,%1,%2,%0;" : "+l"(acc[0][0]) : "l"(ap), "l"(b0));
            asm("fma.rn.f32x2 %0,%1,%2,%0;" : "+l"(acc[0][1]) : "l"(ap), "l"(b1));
            asm("mov.b64 %0,{%1,%1};" : "=l"(ap) : "f"(av.y));
            asm("fma.rn.f32x2 %0,%1,%2,%0;" : "+l"(acc[1][0]) : "l"(ap), "l"(b0));
            asm("fma.rn.f32x2 %0,%1,%2,%0;" : "+l"(acc[1][1]) : "l"(ap), "l"(b1));
            asm("mov.b64 %0,{%1,%1};" : "=l"(ap) : "f"(av.z));
            asm("fma.rn.f32x2 %0,%1,%2,%0;" : "+l"(acc[2][0]) : "l"(ap), "l"(b0));
            asm("fma.rn.f32x2 %0,%1,%2,%0;" : "+l"(acc[2][1]) : "l"(ap), "l"(b1));
            asm("mov.b64 %0,{%1,%1};" : "=l"(ap) : "f"(av.w));
            asm("fma.rn.f32x2 %0,%1,%2,%0;" : "+l"(acc[3][0]) : "l"(ap), "l"(b0));
            asm("fma.rn.f32x2 %0,%1,%2,%0;" : "+l"(acc[3][1]) : "l"(ap), "l"(b1));
        }
        if (kt < KT - 1) {
            int nb = buf ^ 1;
            if (t < 128) {
                As[nb][lp+0][lr]=a4.x; As[nb][lp+1][lr]=a4.y; As[nb][lp+2][lr]=a4.z; As[nb][lp+3][lr]=a4.w;
                Bs[nb][lp+0][lr]=b4.x; Bs[nb][lp+1][lr]=b4.y; Bs[nb][lp+2][lr]=b4.z; Bs[nb][lp+3][lr]=b4.w;
            }
            buf = nb;
        }
        __syncthreads();
    }
#pragma unroll
    for (int i = 0; i < 4; i++) {
        int row = m0 + ty * 4 + i;
#pragma unroll
        for (int jp = 0; jp < 2; jp++) {
            float l, hv;
            asm("mov.b64 {%0,%1},%2;" : "=f"(l), "=f"(hv) : "l"(acc[i][jp]));
            int c0 = n0 + tx * 4 + jp * 2;
            g_hW[row * HH + c0]     = l  + be[c0];
            g_hW[row * HH + c0 + 1] = hv + be[c0 + 1];
        }
    }
}

// ================== mma core: fp16 2-term, A hi only ==================
// buffer: A(0,16K) BH(16K) BL(16K); BUFSZ=48K; double buffered
#define BUFSZ 49152u
#define B_HI  16384u
#define B_LO  32768u

__device__ __forceinline__ void mma_chunk2(float acc[2][8][4], uint32_t bb,
                                           int wm, int wn, int lane) {
#pragma unroll
    for (int ks = 0; ks < 4; ks++) {
        uint32_t bh[4][4], bl[4][4];
        int mm = lane >> 3, ch = mm & 1;
        int rhalf = ((mm >> 1) << 3) + (lane & 7);
#pragma unroll
        for (int p = 0; p < 4; p++) {
            uint32_t off = (uint32_t)(wn * 64 + p * 16 + rhalf) * 128 + ks * 32 + ch * 16;
            uint32_t so = swz(off);
            ldsm4(bh[p], bb + B_HI + so);
            ldsm4(bl[p], bb + B_LO + so);
        }
#pragma unroll
        for (int mt = 0; mt < 2; mt++) {
            uint32_t offa = (uint32_t)(wm * 32 + mt * 16 + (lane & 15)) * 128
                          + ks * 32 + (lane >> 4) * 16;
            uint32_t soa = swz(offa);
            uint32_t ah[4];
            ldsm4(ah, bb + soa);
#pragma unroll
            for (int nt = 0; nt < 8; nt++)
                mma16816(acc[mt][nt], ah, &bh[nt >> 1][(nt & 1) * 2]);
#pragma unroll
            for (int nt = 0; nt < 8; nt++)
                mma16816(acc[mt][nt], ah, &bl[nt >> 1][(nt & 1) * 2]);
        }
    }
}

// ---------------- kernel 2: scores GEMM (pure cp.async + HMMA) ----------------
// grid (4, 256): nq = 128-col quarter of U_e, b = batch. M = 128 objects, K=512.
__global__ void __launch_bounds__(256, 1)
k_scores_mma(const float* __restrict__ w) {
    extern __shared__ __align__(1024) char smem[];
    uint32_t S = smem_u32(smem);
    const int t = threadIdx.x, wid = t >> 5, lane = t & 31;
    const int wm = wid >> 1, wn = wid & 1;
    const int nq = blockIdx.x, b = blockIdx.y;
    const int n0 = nq * 128;

    const uint32_t OFF_HW = 0, OFF_W = 512, OFF_RS = 1024, OFF_BUF = 2048;
    float* hWs = (float*)(smem + OFF_HW);
    float* ws  = (float*)(smem + OFF_W);
    float* rs  = (float*)(smem + OFF_RS);

    if (t < 128) { hWs[t] = g_hW[b * HH + n0 + t]; ws[t] = w[n0 + t]; }

    const int row_ = t >> 1;                  // 0..127 (thread pairs per row)
    const int c8a = (t & 1) * 4;              // base 16B-chunk within row half
    auto prefetch = [&](int kc, int buf) {
        uint32_t Sb = S + OFF_BUF + buf * BUFSZ;
        const __half* Asrc = g_xjh + (size_t)(b * O_ + row_) * HH + kc * 64;
        const __half* BHsrc = g_UeH + (size_t)(n0 + row_) * HH + kc * 64;
        const __half* BLsrc = g_UeL + (size_t)(n0 + row_) * HH + kc * 64;
#pragma unroll
        for (int j = 0; j < 4; j++) {
            uint32_t off = swz((uint32_t)row_ * 128 + (c8a + j) * 16);
            cp16(Sb + off,        Asrc + (c8a + j) * 8);
            cp16(Sb + B_HI + off, BHsrc + (c8a + j) * 8);
            cp16(Sb + B_LO + off, BLsrc + (c8a + j) * 8);
        }
        CP_COMMIT();
    };

    float acc[2][8][4] = {};
    prefetch(0, 0);
    for (int c = 0; c < 8; c++) {
        CP_WAIT0();
        __syncthreads();
        if (c + 1 < 8) prefetch(c + 1, (c + 1) & 1);
        mma_chunk2(acc, S + OFF_BUF + (c & 1) * BUFSZ, wm, wn, lane);
    }

    // epilogue: tanh(C + hW) * w, reduce over 128 cols
    int g = lane >> 2, q = lane & 3;
#pragma unroll
    for (int mt = 0; mt < 2; mt++) {
        float sA = 0.f, sB = 0.f;
#pragma unroll
        for (int nt = 0; nt < 8; nt++) {
            int col = wn * 64 + nt * 8 + q * 2;
            sA += tanhf(acc[mt][nt][0] + hWs[col])     * ws[col];
            sA += tanhf(acc[mt][nt][1] + hWs[col + 1]) * ws[col + 1];
            sB += tanhf(acc[mt][nt][2] + hWs[col])     * ws[col];
            sB += tanhf(acc[mt][nt][3] + hWs[col + 1]) * ws[col + 1];
        }
        sA += __shfl_xor_sync(0xffffffffu, sA, 1);
        sA += __shfl_xor_sync(0xffffffffu, sA, 2);
        sB += __shfl_xor_sync(0xffffffffu, sB, 1);
        sB += __shfl_xor_sync(0xffffffffu, sB, 2);
        if (q == 0) {
            int r0 = wm * 32 + mt * 16 + g;
            rs[wn * 128 + r0]     = sA;
            rs[wn * 128 + r0 + 8] = sB;
        }
    }
    __syncthreads();
    if (t < 128)
        g_partial[(b * O_ + t) * 4 + nq] = rs[t] + rs[128 + t];
}

// ---------------- kernel 3: fused softmax + phi + z-gather (fp16 out) ----------------
__global__ void __launch_bounds__(512, 2)
k_attn_z(const void* __restrict__ mask, const float* __restrict__ XF,
         const float* __restrict__ h, const float* __restrict__ c) {
    __shared__ float sa[128], redm[128], reds[128], phis[512];
    int b = blockIdx.x, t = threadIdx.x;  // 512 threads
    float s = 0.f, e = 0.f;
    if (t < 128) {
        const float* pr = g_partial + (b * O_ + t) * 4;
        s = pr[0] + pr[1] + pr[2] + pr[3];
        int mf = g_mflag;
        bool mv;
        int mi = b * O_ + t;
        if (mf == 1)      mv = ((const float*)mask)[mi] != 0.0f;
        else if (mf == 2) mv = ((const int*)mask)[mi] != 0;
        else              mv = ((const unsigned char*)mask)[mi] != 0;
        if (!mv) s = -1e9f;
        redm[t] = s;
    }
    __syncthreads();
    for (int off = 64; off > 0; off >>= 1) {
        if (t < off) redm[t] = fmaxf(redm[t], redm[t + off]);
        __syncthreads();
    }
    float mx = redm[0];
    if (t < 128) { e = expf(s - mx); reds[t] = e; }
    __syncthreads();
    for (int off = 64; off > 0; off >>= 1) {
        if (t < off) reds[t] += reds[t + off];
        __syncthreads();
    }
    if (t < 128) sa[t] = e / reds[0];
    __syncthreads();

    // phi: thread t owns column t (512 cols), fp16 x_j
    float acc = 0.f;
    const __half* X = g_xjh + (size_t)b * O_ * HH;
    for (int o = 0; o < O_; o++)
        acc += sa[o] * __half2float(X[(size_t)o * HH + t]);
    phis[t] = acc;
    __syncthreads();

    // z fp16: 8 elems per thread
    int j0 = t * 8;
    float v[8];
    if (j0 < 512) {
#pragma unroll
        for (int k = 0; k < 8; k++) v[k] = phis[j0 + k];
    } else if (j0 < 2048) {
        const float* p = XF + (size_t)b * DFF + (j0 - 512);
        float4 a = *(const float4*)p, bq = *(const float4*)(p + 4);
        v[0]=a.x; v[1]=a.y; v[2]=a.z; v[3]=a.w; v[4]=bq.x; v[5]=bq.y; v[6]=bq.z; v[7]=bq.w;
    } else if (j0 < 3072) {
        const float* p = h + (size_t)b * H_ + (j0 - 2048);
        float4 a = *(const float4*)p, bq = *(const float4*)(p + 4);
        v[0]=a.x; v[1]=a.y; v[2]=a.z; v[3]=a.w; v[4]=bq.x; v[5]=bq.y; v[6]=bq.z; v[7]=bq.w;
    } else {
        const float* p = c + (size_t)b * H_ + (j0 - 3072);
        float4 a = *(const float4*)p, bq = *(const float4*)(p + 4);
        v[0]=a.x; v[1]=a.y; v[2]=a.z; v[3]=a.w; v[4]=bq.x; v[5]=bq.y; v[6]=bq.z; v[7]=bq.w;
    }
    uint4 o;
    o.x = pk2(v[0], v[1]); o.y = pk2(v[2], v[3]);
    o.z = pk2(v[4], v[5]); o.w = pk2(v[6], v[7]);
    *(uint4*)(g_zh + (size_t)b * 4096 + j0) = o;
}

// ---------------- kernel 4: gates GEMM (A=fp16 z via cp.async, B inline split) ------
// grid (32, 2, 2): bx = n-block(128), by = m-block(128), bz = K split
__global__ void __launch_bounds__(256, 1)
k_gates_mma(const float* __restrict__ Wi, const float* __restrict__ Wf,
            const float* __restrict__ Wc, const float* __restrict__ Wo,
            const float* __restrict__ Ui, const float* __restrict__ Uf,
            const float* __restrict__ Uc, const float* __restrict__ Uo,
            const float* __restrict__ Vi, const float* __restrict__ Vf,
            const float* __restrict__ Vo) {
    extern __shared__ __align__(1024) char smem[];
    uint32_t S = smem_u32(smem);
    const int t = threadIdx.x, wid = t >> 5, lane = t & 31;
    const int wm = wid >> 1, wn = wid & 1;
    const int nb_ = blockIdx.x, mb = blockIdx.y, ksp = blockIdx.z;
    const int n0g = nb_ * 128;
    const int gg = n0g >> 10;
    const int jb = n0g & 1023;
    const float* Wg = (gg == 0) ? Wi : (gg == 1) ? Wf : (gg == 2) ? Wc : Wo;
    const float* Ug = (gg == 0) ? Ui : (gg == 1) ? Uf : (gg == 2) ? Uc : Uo;
    const float* Vg = (gg == 0) ? Vi : (gg == 1) ? Vf : (gg == 3) ? Vo : nullptr;

    const int row_ = t >> 1;
    const int c8a = (t & 1) * 4;
    auto prefetchA = [&](int kc, int buf) {
        uint32_t Sb = S + buf * BUFSZ;
        const __half* Asrc = g_zh + (size_t)(mb * 128 + row_) * 4096
                           + ksp * 2048 + kc * 64;
#pragma unroll
        for (int j = 0; j < 4; j++) {
            uint32_t off = swz((uint32_t)row_ * 128 + (c8a + j) * 16);
            cp16(Sb + off, Asrc + (c8a + j) * 8);
        }
        CP_COMMIT();
    };

    float4 pb[8];
    auto loadB = [&](int kc) {
        int kk0 = ksp * 2048 + kc * 64;
        const float* bp = nullptr; int rstride = 0; bool zer = false;
        if (kk0 < 2048)      { bp = Wg + kk0;          rstride = 2048; }
        else if (kk0 < 3072) { bp = Ug + (kk0 - 2048); rstride = 1024; }
        else if (Vg)         { bp = Vg + (kk0 - 3072); rstride = 1024; }
        else                 { zer = true; }
#pragma unroll
        for (int i = 0; i < 8; i++) {
            int idx = i * 256 + t, row = idx >> 4, f4 = idx & 15;
            pb[i] = zer ? make_float4(0, 0, 0, 0)
                        : *(const float4*)(bp + (size_t)(jb + row) * rstride + f4 * 4);
        }
    };
    auto stsB = [&](int buf) {
        char* base = smem + buf * BUFSZ;
#pragma unroll
        for (int i = 0; i < 8; i++) {
            int idx = i * 256 + t, row = idx >> 4, f4 = idx & 15;
            cvt_f16split(base + B_HI, base + B_LO, (uint32_t)row * 128 + f4 * 8, pb[i]);
        }
    };

    float acc[2][8][4] = {};
    loadB(0);
    stsB(0);
    prefetchA(0, 0);
    for (int c = 0; c < 32; c++) {
        CP_WAIT0();
        __syncthreads();
        if (c + 1 < 32) { loadB(c + 1); prefetchA(c + 1, (c + 1) & 1); }
        mma_chunk2(acc, S + (c & 1) * BUFSZ, wm, wn, lane);
        if (c + 1 < 32) stsB((c + 1) & 1);
    }

    // epilogue: store fp32 partials
    int g = lane >> 2, q = lane & 3;
#pragma unroll
    for (int mt = 0; mt < 2; mt++) {
        int m = mb * 128 + wm * 32 + mt * 16 + g;
        float* baseA = g_gp + (size_t)(ksp * B_ + m) * 4096 + n0g;
        float* baseB = g_gp + (size_t)(ksp * B_ + m + 8) * 4096 + n0g;
#pragma unroll
        for (int nt = 0; nt < 8; nt++) {
            int col = wn * 64 + nt * 8 + q * 2;
            *(float2*)(baseA + col) = make_float2(acc[mt][nt][0], acc[mt][nt][1]);
            *(float2*)(baseB + col) = make_float2(acc[mt][nt][2], acc[mt][nt][3]);
        }
    }
}

// ---------------- kernel 5: elementwise LSTM update ----------------
__global__ void k_final(const float* __restrict__ c,
                        const float* __restrict__ bi, const float* __restrict__ bf,
                        const float* __restrict__ bc, const float* __restrict__ bo,
                        float* __restrict__ out) {
    int idx = blockIdx.x * 256 + threadIdx.x;
    int b = idx >> 10, j = idx & 1023;
    const float* gA = g_gp + (size_t)b * 4096;
    const float* gB = g_gp + (size_t)(B_ + b) * 4096;
    float gi = gA[j]        + gB[j]        + bi[j];
    float gf = gA[1024 + j] + gB[1024 + j] + bf[j];
    float gc = gA[2048 + j] + gB[2048 + j] + bc[j];
    float go = gA[3072 + j] + gB[3072 + j] + bo[j];
    float si = sigmoidf_(gi);
    float sf = sigmoidf_(gf);
    float so = sigmoidf_(go);
    float cold = c[idx];
    float nc = sf * cold + si * tanhf(gc);
    float nh = so * tanhf(nc);
    out[idx] = nh;
    out[B_ * H_ + idx] = nc;
}

// ---------------- launch ----------------
extern "C" void kernel_launch(void* const* d_in, const int* in_sizes, int n_in,
                              void* d_out, int out_size) {
    const float* x_j  = (const float*)d_in[0];
    const void*  mask = d_in[1];
    const float* X_F  = (const float*)d_in[2];
    const float* h    = (const float*)d_in[3];
    const float* c    = (const float*)d_in[4];
    const float* W_i  = (const float*)d_in[5];
    const float* W_f  = (const float*)d_in[6];
    const float* W_c  = (const float*)d_in[7];
    const float* W_o  = (const float*)d_in[8];
    const float* U_i  = (const float*)d_in[9];
    const float* U_f  = (const float*)d_in[10];
    const float* U_c  = (const float*)d_in[11];
    const float* U_o  = (const float*)d_in[12];
    const float* V_i  = (const float*)d_in[13];
    const float* V_f  = (const float*)d_in[14];
    const float* V_o  = (const float*)d_in[16];
    const float* b_i  = (const float*)d_in[17];
    const float* b_f  = (const float*)d_in[18];
    const float* b_c  = (const float*)d_in[19];
    const float* b_o  = (const float*)d_in[20];
    const float* w    = (const float*)d_in[21];
    const float* W_e  = (const float*)d_in[22];
    const float* U_e  = (const float*)d_in[23];
    const float* b_e  = (const float*)d_in[24];

    cudaFuncSetAttribute(k_scores_mma, cudaFuncAttributeMaxDynamicSharedMemorySize, 100352);
    cudaFuncSetAttribute(k_gates_mma,  cudaFuncAttributeMaxDynamicSharedMemorySize, 98304);

    k_sniff<<<1, 256>>>((const unsigned char*)mask);
    k_cvt_xj<<<8192, 256>>>(x_j);
    k_cvt_ue<<<128, 256>>>(U_e);
    k_hW<<<dim3(8, 4), 256>>>(h, W_e, b_e);
    k_scores_mma<<<dim3(4, 256), 256, 100352>>>(w);
    k_attn_z<<<256, 512>>>(mask, X_F, h, c);
    k_gates_mma<<<dim3(32, 2, 2), 256, 98304>>>(W_i, W_f, W_c, W_o,
                                                U_i, U_f, U_c, U_o,
                                                V_i, V_f, V_o);
    k_final<<<1024, 256>>>(c, b_i, b_f, b_c, b_o, (float*)d_out);
}

// round 11
// speedup vs baseline: 5.0238x; 1.5543x over previous
#include <cuda_runtime.h>
#include <cuda_fp16.h>
#include <cstdint>

// Problem constants
#define B_  256
#define O_  128
#define H_  1024
#define HH  512
#define I_  2048
#define DFF 1536

typedef unsigned long long u64;

// ---------------- device scratch ----------------
__device__ __align__(16) float g_hW[4 * B_ * HH];      // split-K partials of h@W_e^T (+b_e in slice 0)
__device__ __align__(16) float g_partial[B_ * O_ * 4]; // score partials
__device__ __align__(16) __half g_xjh[B_ * O_ * HH];   // x_j in fp16 (32MB)
__device__ __align__(16) __half g_UeH[HH * HH];        // U_e fp16
__device__ __align__(16) __half g_zh[B_ * 4096];       // [phi|X_F|h|c] fp16
__device__ __align__(16) float g_gp[2 * B_ * 4096];    // split-K gate partials
__device__ int g_mflag;

// ---------------- helpers ----------------
__device__ __forceinline__ uint32_t smem_u32(const void* p) {
    uint32_t a;
    asm("{ .reg .u64 t; cvta.to.shared.u64 t, %1; cvt.u32.u64 %0, t; }" : "=r"(a) : "l"(p));
    return a;
}
__device__ __forceinline__ uint32_t swz(uint32_t off) { return off ^ ((off >> 3) & 0x70); }

__device__ __forceinline__ void ldsm4(uint32_t* r, uint32_t addr) {
    asm volatile("ldmatrix.sync.aligned.m8n8.x4.shared.b16 {%0,%1,%2,%3},[%4];"
        : "=r"(r[0]), "=r"(r[1]), "=r"(r[2]), "=r"(r[3]) : "r"(addr));
}
__device__ __forceinline__ void mma16816(float* c, const uint32_t* a, const uint32_t* b) {
    asm volatile("mma.sync.aligned.m16n8k16.row.col.f32.f16.f16.f32 "
        "{%0,%1,%2,%3},{%4,%5,%6,%7},{%8,%9},{%0,%1,%2,%3};"
        : "+f"(c[0]), "+f"(c[1]), "+f"(c[2]), "+f"(c[3])
        : "r"(a[0]), "r"(a[1]), "r"(a[2]), "r"(a[3]), "r"(b[0]), "r"(b[1]));
}
__device__ __forceinline__ void cp16(uint32_t dst, const void* src) {
    asm volatile("cp.async.cg.shared.global [%0],[%1],16;" :: "r"(dst), "l"(src));
}
#define CP_COMMIT() asm volatile("cp.async.commit_group;" ::: "memory")
#define CP_WAIT0()  asm volatile("cp.async.wait_group 0;" ::: "memory")

__device__ __forceinline__ uint32_t pk2(float a, float b) {
    __half2 x = __floats2half2_rn(a, b);
    uint32_t r; memcpy(&r, &x, 4); return r;
}
__device__ __forceinline__ float sigmoidf_(float x) { return 1.0f / (1.0f + expf(-x)); }

// fp16 hi/lo split of a float4, stored swizzled as u64 each
__device__ __forceinline__ void cvt_f16split(char* hib, char* lob, uint32_t off, float4 v) {
    uint32_t so = swz(off);
    __half2 h0 = __floats2half2_rn(v.x, v.y);
    __half2 h1 = __floats2half2_rn(v.z, v.w);
    float2 f0 = __half22float2(h0), f1 = __half22float2(h1);
    uint32_t l0 = pk2(v.x - f0.x, v.y - f0.y);
    uint32_t l1 = pk2(v.z - f1.x, v.w - f1.y);
    uint32_t hh0, hh1; memcpy(&hh0, &h0, 4); memcpy(&hh1, &h1, 4);
    *(u64*)(hib + so) = (u64)hh0 | ((u64)hh1 << 32);
    *(u64*)(lob + so) = (u64)l0  | ((u64)l1  << 32);
}

// ---------------- kernel 0: sniff mask dtype ----------------
__global__ void k_sniff(const unsigned char* __restrict__ m) {
    __shared__ int anyBig, off123;
    if (threadIdx.x == 0) { anyBig = 0; off123 = 0; }
    __syncthreads();
    int big = 0, o123 = 0;
    for (int i = threadIdx.x; i < 4096; i += blockDim.x) {
        unsigned char v = m[i];
        if (v >= 2) big = 1;
        if ((i & 3) != 0 && v != 0) o123 = 1;
    }
    if (big) atomicOr(&anyBig, 1);
    if (o123) atomicOr(&off123, 1);
    __syncthreads();
    if (threadIdx.x == 0) g_mflag = anyBig ? 1 : (off123 ? 0 : 2);
}

// ---------------- conversion kernels ----------------
__global__ void k_cvt_xj(const float* __restrict__ xj) {
    size_t i = ((size_t)blockIdx.x * 256 + threadIdx.x) * 8;
    float4 v0 = *(const float4*)(xj + i);
    float4 v1 = *(const float4*)(xj + i + 4);
    uint4 o;
    o.x = pk2(v0.x, v0.y); o.y = pk2(v0.z, v0.w);
    o.z = pk2(v1.x, v1.y); o.w = pk2(v1.z, v1.w);
    *(uint4*)(g_xjh + i) = o;
}
__global__ void k_cvt_ue(const float* __restrict__ Ue) {
    size_t i = ((size_t)blockIdx.x * 256 + threadIdx.x) * 8;
    float4 v0 = *(const float4*)(Ue + i);
    float4 v1 = *(const float4*)(Ue + i + 4);
    uint4 hi;
    hi.x = pk2(v0.x, v0.y); hi.y = pk2(v0.z, v0.w);
    hi.z = pk2(v1.x, v1.y); hi.w = pk2(v1.z, v1.w);
    *(uint4*)(g_UeH + i) = hi;
}

// ---------------- kernel 1: g_hW partials = h @ W_e^T (split-K=4) ----------------
// grid (8, 4, 4): n-tile 64, m-tile 64, K slice 256. Slice 0 adds b_e.
__global__ void __launch_bounds__(256, 2)
k_hW(const float* __restrict__ h, const float* __restrict__ We,
     const float* __restrict__ be) {
    __shared__ __align__(16) float As[2][8][64];
    __shared__ __align__(16) float Bs[2][8][64];
    int t = threadIdx.x;
    int m0 = blockIdx.y * 64, n0 = blockIdx.x * 64;
    int ks = blockIdx.z;
    int tx = t & 15, ty = t >> 4;
    int lr = t >> 1, lp = (t & 1) * 4;
    const float* Ap = h  + (m0 + lr) * H_ + ks * 256 + lp;
    const float* Bp = We + (n0 + lr) * H_ + ks * 256 + lp;

    u64 acc[4][2] = {};
    float4 a4 = make_float4(0,0,0,0), b4 = make_float4(0,0,0,0);
    if (t < 128) { a4 = *(const float4*)Ap; b4 = *(const float4*)Bp; }
    if (t < 128) {
        As[0][lp+0][lr]=a4.x; As[0][lp+1][lr]=a4.y; As[0][lp+2][lr]=a4.z; As[0][lp+3][lr]=a4.w;
        Bs[0][lp+0][lr]=b4.x; Bs[0][lp+1][lr]=b4.y; Bs[0][lp+2][lr]=b4.z; Bs[0][lp+3][lr]=b4.w;
    }
    __syncthreads();
    int buf = 0;
    const int KT = 256 / 8;
    for (int kt = 0; kt < KT; kt++) {
        if (kt < KT - 1 && t < 128) {
            a4 = *(const float4*)(Ap + (kt + 1) * 8);
            b4 = *(const float4*)(Bp + (kt + 1) * 8);
        }
#pragma unroll
        for (int kk = 0; kk < 8; kk++) {
            float4 av = *(const float4*)&As[buf][kk][ty * 4];
            u64 b0 = *(const u64*)&Bs[buf][kk][tx * 4];
            u64 b1 = *(const u64*)&Bs[buf][kk][tx * 4 + 2];
            u64 ap;
            asm("mov.b64 %0,{%1,%1};" : "=l"(ap) : "f"(av.x));
            asm("fma.rn.f32x2 %0,%1,%2,%0;" : "+l"(acc[0][0]) : "l"(ap), "l"(b0));
            asm("fma.rn.f32x2 %0,%1,%2,%0;" : "+l"(acc[0][1]) : "l"(ap), "l"(b1));
            asm("mov.b64 %0,{%1,%1};" : "=l"(ap) : "f"(av.y));
            asm("fma.rn.f32x2 %0,%1,%2,%0;" : "+l"(acc[1][0]) : "l"(ap), "l"(b0));
            asm("fma.rn.f32x2 %0,%1,%2,%0;" : "+l"(acc[1][1]) : "l"(ap), "l"(b1));
            asm("mov.b64 %0,{%1,%1};" : "=l"(ap) : "f"(av.z));
            asm("fma.rn.f32x2 %0,%1,%2,%0;" : "+l"(acc[2][0]) : "l"(ap), "l"(b0));
            asm("fma.rn.f32x2 %0,%1,%2,%0;" : "+l"(acc[2][1]) : "l"(ap), "l"(b1));
            asm("mov.b64 %0,{%1,%1};" : "=l"(ap) : "f"(av.w));
            asm("fma.rn.f32x2 %0,%1,%2,%0;" : "+l"(acc[3][0]) : "l"(ap), "l"(b0));
            asm("fma.rn.f32x2 %0,%1,%2,%0;" : "+l"(acc[3][1]) : "l"(ap), "l"(b1));
        }
        if (kt < KT - 1) {
            int nb = buf ^ 1;
            if (t < 128) {
                As[nb][lp+0][lr]=a4.x; As[nb][lp+1][lr]=a4.y; As[nb][lp+2][lr]=a4.z; As[nb][lp+3][lr]=a4.w;
                Bs[nb][lp+0][lr]=b4.x; Bs[nb][lp+1][lr]=b4.y; Bs[nb][lp+2][lr]=b4.z; Bs[nb][lp+3][lr]=b4.w;
            }
            buf = nb;
        }
        __syncthreads();
    }
    float* outp = g_hW + (size_t)ks * B_ * HH;
#pragma unroll
    for (int i = 0; i < 4; i++) {
        int row = m0 + ty * 4 + i;
#pragma unroll
        for (int jp = 0; jp < 2; jp++) {
            float l, hv;
            asm("mov.b64 {%0,%1},%2;" : "=f"(l), "=f"(hv) : "l"(acc[i][jp]));
            int c0 = n0 + tx * 4 + jp * 2;
            float bb0 = (ks == 0) ? be[c0] : 0.f;
            float bb1 = (ks == 0) ? be[c0 + 1] : 0.f;
            outp[row * HH + c0]     = l  + bb0;
            outp[row * HH + c0 + 1] = hv + bb1;
        }
    }
}

// ================== mma cores ==================
// gates buffer: A(0..16K) BH(16K..32K) BL(32K..48K); BUFSZ=48K
#define BUFSZ 49152u
#define B_HI  16384u
#define B_LO  32768u
// scores buffer: A(0..16K) BH(16K..32K); BUFSZ_S=32K
#define BUFSZ_S 32768u

// single-term fp16 (scores)
__device__ __forceinline__ void mma_chunk1(float acc[2][8][4], uint32_t bb,
                                           int wm, int wn, int lane) {
#pragma unroll
    for (int ks = 0; ks < 4; ks++) {
        uint32_t bh[4][4];
        int mm = lane >> 3, ch = mm & 1;
        int rhalf = ((mm >> 1) << 3) + (lane & 7);
#pragma unroll
        for (int p = 0; p < 4; p++) {
            uint32_t off = (uint32_t)(wn * 64 + p * 16 + rhalf) * 128 + ks * 32 + ch * 16;
            ldsm4(bh[p], bb + B_HI + swz(off));
        }
#pragma unroll
        for (int mt = 0; mt < 2; mt++) {
            uint32_t offa = (uint32_t)(wm * 32 + mt * 16 + (lane & 15)) * 128
                          + ks * 32 + (lane >> 4) * 16;
            uint32_t ah[4];
            ldsm4(ah, bb + swz(offa));
#pragma unroll
            for (int nt = 0; nt < 8; nt++)
                mma16816(acc[mt][nt], ah, &bh[nt >> 1][(nt & 1) * 2]);
        }
    }
}

// 2-term fp16, B split (gates)
__device__ __forceinline__ void mma_chunk2(float acc[2][8][4], uint32_t bb,
                                           int wm, int wn, int lane) {
#pragma unroll
    for (int ks = 0; ks < 4; ks++) {
        uint32_t bh[4][4], bl[4][4];
        int mm = lane >> 3, ch = mm & 1;
        int rhalf = ((mm >> 1) << 3) + (lane & 7);
#pragma unroll
        for (int p = 0; p < 4; p++) {
            uint32_t off = (uint32_t)(wn * 64 + p * 16 + rhalf) * 128 + ks * 32 + ch * 16;
            uint32_t so = swz(off);
            ldsm4(bh[p], bb + B_HI + so);
            ldsm4(bl[p], bb + B_LO + so);
        }
#pragma unroll
        for (int mt = 0; mt < 2; mt++) {
            uint32_t offa = (uint32_t)(wm * 32 + mt * 16 + (lane & 15)) * 128
                          + ks * 32 + (lane >> 4) * 16;
            uint32_t soa = swz(offa);
            uint32_t ah[4];
            ldsm4(ah, bb + soa);
#pragma unroll
            for (int nt = 0; nt < 8; nt++)
                mma16816(acc[mt][nt], ah, &bh[nt >> 1][(nt & 1) * 2]);
#pragma unroll
            for (int nt = 0; nt < 8; nt++)
                mma16816(acc[mt][nt], ah, &bl[nt >> 1][(nt & 1) * 2]);
        }
    }
}

// ---------------- kernel 2: scores GEMM (single-term fp16, occ 2) ----------------
// grid (4, 256): nq = 128-col quarter of U_e, b = batch. M = 128 objects, K=512.
__global__ void __launch_bounds__(256, 2)
k_scores_mma(const float* __restrict__ w) {
    extern __shared__ __align__(1024) char smem[];
    uint32_t S = smem_u32(smem);
    const int t = threadIdx.x, wid = t >> 5, lane = t & 31;
    const int wm = wid >> 1, wn = wid & 1;
    const int nq = blockIdx.x, b = blockIdx.y;
    const int n0 = nq * 128;

    const uint32_t OFF_HW = 0, OFF_W = 512, OFF_RS = 1024, OFF_BUF = 2048;
    float* hWs = (float*)(smem + OFF_HW);
    float* ws  = (float*)(smem + OFF_W);
    float* rs  = (float*)(smem + OFF_RS);

    if (t < 128) {
        int idx = b * HH + n0 + t;
        hWs[t] = g_hW[idx] + g_hW[B_ * HH + idx]
               + g_hW[2 * B_ * HH + idx] + g_hW[3 * B_ * HH + idx];
        ws[t] = w[n0 + t];
    }

    const int row_ = t >> 1;                  // 0..127 (thread pairs per row)
    const int c8a = (t & 1) * 4;              // base 16B-chunk within row half
    auto prefetch = [&](int kc, int buf) {
        uint32_t Sb = S + OFF_BUF + buf * BUFSZ_S;
        const __half* Asrc = g_xjh + (size_t)(b * O_ + row_) * HH + kc * 64;
        const __half* BHsrc = g_UeH + (size_t)(n0 + row_) * HH + kc * 64;
#pragma unroll
        for (int j = 0; j < 4; j++) {
            uint32_t off = swz((uint32_t)row_ * 128 + (c8a + j) * 16);
            cp16(Sb + off,        Asrc + (c8a + j) * 8);
            cp16(Sb + B_HI + off, BHsrc + (c8a + j) * 8);
        }
        CP_COMMIT();
    };

    float acc[2][8][4] = {};
    prefetch(0, 0);
    for (int c = 0; c < 8; c++) {
        CP_WAIT0();
        __syncthreads();
        if (c + 1 < 8) prefetch(c + 1, (c + 1) & 1);
        mma_chunk1(acc, S + OFF_BUF + (c & 1) * BUFSZ_S, wm, wn, lane);
    }

    // epilogue: tanh(C + hW) * w, reduce over 128 cols
    int g = lane >> 2, q = lane & 3;
#pragma unroll
    for (int mt = 0; mt < 2; mt++) {
        float sA = 0.f, sB = 0.f;
#pragma unroll
        for (int nt = 0; nt < 8; nt++) {
            int col = wn * 64 + nt * 8 + q * 2;
            sA += tanhf(acc[mt][nt][0] + hWs[col])     * ws[col];
            sA += tanhf(acc[mt][nt][1] + hWs[col + 1]) * ws[col + 1];
            sB += tanhf(acc[mt][nt][2] + hWs[col])     * ws[col];
            sB += tanhf(acc[mt][nt][3] + hWs[col + 1]) * ws[col + 1];
        }
        sA += __shfl_xor_sync(0xffffffffu, sA, 1);
        sA += __shfl_xor_sync(0xffffffffu, sA, 2);
        sB += __shfl_xor_sync(0xffffffffu, sB, 1);
        sB += __shfl_xor_sync(0xffffffffu, sB, 2);
        if (q == 0) {
            int r0 = wm * 32 + mt * 16 + g;
            rs[wn * 128 + r0]     = sA;
            rs[wn * 128 + r0 + 8] = sB;
        }
    }
    __syncthreads();
    if (t < 128)
        g_partial[(b * O_ + t) * 4 + nq] = rs[t] + rs[128 + t];
}

// ---------------- kernel 3: fused softmax + phi + z-gather (fp16 out) ----------------
__global__ void __launch_bounds__(512, 2)
k_attn_z(const void* __restrict__ mask, const float* __restrict__ XF,
         const float* __restrict__ h, const float* __restrict__ c) {
    __shared__ float sa[128], redm[128], reds[128], phis[512];
    int b = blockIdx.x, t = threadIdx.x;  // 512 threads
    float s = 0.f, e = 0.f;
    if (t < 128) {
        const float* pr = g_partial + (b * O_ + t) * 4;
        s = pr[0] + pr[1] + pr[2] + pr[3];
        int mf = g_mflag;
        bool mv;
        int mi = b * O_ + t;
        if (mf == 1)      mv = ((const float*)mask)[mi] != 0.0f;
        else if (mf == 2) mv = ((const int*)mask)[mi] != 0;
        else              mv = ((const unsigned char*)mask)[mi] != 0;
        if (!mv) s = -1e9f;
        redm[t] = s;
    }
    __syncthreads();
    for (int off = 64; off > 0; off >>= 1) {
        if (t < off) redm[t] = fmaxf(redm[t], redm[t + off]);
        __syncthreads();
    }
    float mx = redm[0];
    if (t < 128) { e = expf(s - mx); reds[t] = e; }
    __syncthreads();
    for (int off = 64; off > 0; off >>= 1) {
        if (t < off) reds[t] += reds[t + off];
        __syncthreads();
    }
    if (t < 128) sa[t] = e / reds[0];
    __syncthreads();

    // phi: thread t owns column t (512 cols), fp16 x_j
    float acc = 0.f;
    const __half* X = g_xjh + (size_t)b * O_ * HH;
    for (int o = 0; o < O_; o++)
        acc += sa[o] * __half2float(X[(size_t)o * HH + t]);
    phis[t] = acc;
    __syncthreads();

    // z fp16: 8 elems per thread
    int j0 = t * 8;
    float v[8];
    if (j0 < 512) {
#pragma unroll
        for (int k = 0; k < 8; k++) v[k] = phis[j0 + k];
    } else if (j0 < 2048) {
        const float* p = XF + (size_t)b * DFF + (j0 - 512);
        float4 a = *(const float4*)p, bq = *(const float4*)(p + 4);
        v[0]=a.x; v[1]=a.y; v[2]=a.z; v[3]=a.w; v[4]=bq.x; v[5]=bq.y; v[6]=bq.z; v[7]=bq.w;
    } else if (j0 < 3072) {
        const float* p = h + (size_t)b * H_ + (j0 - 2048);
        float4 a = *(const float4*)p, bq = *(const float4*)(p + 4);
        v[0]=a.x; v[1]=a.y; v[2]=a.z; v[3]=a.w; v[4]=bq.x; v[5]=bq.y; v[6]=bq.z; v[7]=bq.w;
    } else {
        const float* p = c + (size_t)b * H_ + (j0 - 3072);
        float4 a = *(const float4*)p, bq = *(const float4*)(p + 4);
        v[0]=a.x; v[1]=a.y; v[2]=a.z; v[3]=a.w; v[4]=bq.x; v[5]=bq.y; v[6]=bq.z; v[7]=bq.w;
    }
    uint4 o;
    o.x = pk2(v[0], v[1]); o.y = pk2(v[2], v[3]);
    o.z = pk2(v[4], v[5]); o.w = pk2(v[6], v[7]);
    *(uint4*)(g_zh + (size_t)b * 4096 + j0) = o;
}

// ---------------- kernel 4: gates GEMM (A=fp16 z via cp.async, B inline split) ------
// grid (32, 2, 2): bx = n-block(128), by = m-block(128), bz = K split
__global__ void __launch_bounds__(256, 1)
k_gates_mma(const float* __restrict__ Wi, const float* __restrict__ Wf,
            const float* __restrict__ Wc, const float* __restrict__ Wo,
            const float* __restrict__ Ui, const float* __restrict__ Uf,
            const float* __restrict__ Uc, const float* __restrict__ Uo,
            const float* __restrict__ Vi, const float* __restrict__ Vf,
            const float* __restrict__ Vo) {
    extern __shared__ __align__(1024) char smem[];
    uint32_t S = smem_u32(smem);
    const int t = threadIdx.x, wid = t >> 5, lane = t & 31;
    const int wm = wid >> 1, wn = wid & 1;
    const int nb_ = blockIdx.x, mb = blockIdx.y, ksp = blockIdx.z;
    const int n0g = nb_ * 128;
    const int gg = n0g >> 10;
    const int jb = n0g & 1023;
    const float* Wg = (gg == 0) ? Wi : (gg == 1) ? Wf : (gg == 2) ? Wc : Wo;
    const float* Ug = (gg == 0) ? Ui : (gg == 1) ? Uf : (gg == 2) ? Uc : Uo;
    const float* Vg = (gg == 0) ? Vi : (gg == 1) ? Vf : (gg == 3) ? Vo : nullptr;

    const int row_ = t >> 1;
    const int c8a = (t & 1) * 4;
    auto prefetchA = [&](int kc, int buf) {
        uint32_t Sb = S + buf * BUFSZ;
        const __half* Asrc = g_zh + (size_t)(mb * 128 + row_) * 4096
                           + ksp * 2048 + kc * 64;
#pragma unroll
        for (int j = 0; j < 4; j++) {
            uint32_t off = swz((uint32_t)row_ * 128 + (c8a + j) * 16);
            cp16(Sb + off, Asrc + (c8a + j) * 8);
        }
        CP_COMMIT();
    };

    float4 pb[8];
    auto loadB = [&](int kc) {
        int kk0 = ksp * 2048 + kc * 64;
        const float* bp = nullptr; int rstride = 0; bool zer = false;
        if (kk0 < 2048)      { bp = Wg + kk0;          rstride = 2048; }
        else if (kk0 < 3072) { bp = Ug + (kk0 - 2048); rstride = 1024; }
        else if (Vg)         { bp = Vg + (kk0 - 3072); rstride = 1024; }
        else                 { zer = true; }
#pragma unroll
        for (int i = 0; i < 8; i++) {
            int idx = i * 256 + t, row = idx >> 4, f4 = idx & 15;
            pb[i] = zer ? make_float4(0, 0, 0, 0)
                        : *(const float4*)(bp + (size_t)(jb + row) * rstride + f4 * 4);
        }
    };
    auto stsB = [&](int buf) {
        char* base = smem + buf * BUFSZ;
#pragma unroll
        for (int i = 0; i < 8; i++) {
            int idx = i * 256 + t, row = idx >> 4, f4 = idx & 15;
            cvt_f16split(base + B_HI, base + B_LO, (uint32_t)row * 128 + f4 * 8, pb[i]);
        }
    };

    float acc[2][8][4] = {};
    loadB(0);
    stsB(0);
    prefetchA(0, 0);
    for (int c = 0; c < 32; c++) {
        CP_WAIT0();
        __syncthreads();
        if (c + 1 < 32) { loadB(c + 1); prefetchA(c + 1, (c + 1) & 1); }
        mma_chunk2(acc, S + (c & 1) * BUFSZ, wm, wn, lane);
        if (c + 1 < 32) stsB((c + 1) & 1);
    }

    // epilogue: store fp32 partials
    int g = lane >> 2, q = lane & 3;
#pragma unroll
    for (int mt = 0; mt < 2; mt++) {
        int m = mb * 128 + wm * 32 + mt * 16 + g;
        float* baseA = g_gp + (size_t)(ksp * B_ + m) * 4096 + n0g;
        float* baseB = g_gp + (size_t)(ksp * B_ + m + 8) * 4096 + n0g;
#pragma unroll
        for (int nt = 0; nt < 8; nt++) {
            int col = wn * 64 + nt * 8 + q * 2;
            *(float2*)(baseA + col) = make_float2(acc[mt][nt][0], acc[mt][nt][1]);
            *(float2*)(baseB + col) = make_float2(acc[mt][nt][2], acc[mt][nt][3]);
        }
    }
}

// ---------------- kernel 5: elementwise LSTM update ----------------
__global__ void k_final(const float* __restrict__ c,
                        const float* __restrict__ bi, const float* __restrict__ bf,
                        const float* __restrict__ bc, const float* __restrict__ bo,
                        float* __restrict__ out) {
    int idx = blockIdx.x * 256 + threadIdx.x;
    int b = idx >> 10, j = idx & 1023;
    const float* gA = g_gp + (size_t)b * 4096;
    const float* gB = g_gp + (size_t)(B_ + b) * 4096;
    float gi = gA[j]        + gB[j]        + bi[j];
    float gf = gA[1024 + j] + gB[1024 + j] + bf[j];
    float gc = gA[2048 + j] + gB[2048 + j] + bc[j];
    float go = gA[3072 + j] + gB[3072 + j] + bo[j];
    float si = sigmoidf_(gi);
    float sf = sigmoidf_(gf);
    float so = sigmoidf_(go);
    float cold = c[idx];
    float nc = sf * cold + si * tanhf(gc);
    float nh = so * tanhf(nc);
    out[idx] = nh;
    out[B_ * H_ + idx] = nc;
}

// ---------------- launch ----------------
extern "C" void kernel_launch(void* const* d_in, const int* in_sizes, int n_in,
                              void* d_out, int out_size) {
    const float* x_j  = (const float*)d_in[0];
    const void*  mask = d_in[1];
    const float* X_F  = (const float*)d_in[2];
    const float* h    = (const float*)d_in[3];
    const float* c    = (const float*)d_in[4];
    const float* W_i  = (const float*)d_in[5];
    const float* W_f  = (const float*)d_in[6];
    const float* W_c  = (const float*)d_in[7];
    const float* W_o  = (const float*)d_in[8];
    const float* U_i  = (const float*)d_in[9];
    const float* U_f  = (const float*)d_in[10];
    const float* U_c  = (const float*)d_in[11];
    const float* U_o  = (const float*)d_in[12];
    const float* V_i  = (const float*)d_in[13];
    const float* V_f  = (const float*)d_in[14];
    const float* V_o  = (const float*)d_in[16];
    const float* b_i  = (const float*)d_in[17];
    const float* b_f  = (const float*)d_in[18];
    const float* b_c  = (const float*)d_in[19];
    const float* b_o  = (const float*)d_in[20];
    const float* w    = (const float*)d_in[21];
    const float* W_e  = (const float*)d_in[22];
    const float* U_e  = (const float*)d_in[23];
    const float* b_e  = (const float*)d_in[24];

    cudaFuncSetAttribute(k_scores_mma, cudaFuncAttributeMaxDynamicSharedMemorySize, 67584);
    cudaFuncSetAttribute(k_gates_mma,  cudaFuncAttributeMaxDynamicSharedMemorySize, 98304);

    k_sniff<<<1, 256>>>((const unsigned char*)mask);
    k_cvt_xj<<<8192, 256>>>(x_j);
    k_cvt_ue<<<128, 256>>>(U_e);
    k_hW<<<dim3(8, 4, 4), 256>>>(h, W_e, b_e);
    k_scores_mma<<<dim3(4, 256), 256, 67584>>>(w);
    k_attn_z<<<256, 512>>>(mask, X_F, h, c);
    k_gates_mma<<<dim3(32, 2, 2), 256, 98304>>>(W_i, W_f, W_c, W_o,
                                                U_i, U_f, U_c, U_o,
                                                V_i, V_f, V_o);
    k_final<<<1024, 256>>>(c, b_i, b_f, b_c, b_o, (float*)d_out);
}

// round 12
// speedup vs baseline: 5.6758x; 1.1298x over previous
#include <cuda_runtime.h>
#include <cuda_fp16.h>
#include <cstdint>

// Problem constants
#define B_  256
#define O_  128
#define H_  1024
#define HH  512
#define I_  2048
#define DFF 1536

typedef unsigned long long u64;

// ---------------- device scratch ----------------
__device__ __align__(16) float g_hW[8 * B_ * HH];      // split-K=8 partials of h@W_e^T (+b_e slice0)
__device__ __align__(16) float g_partial[B_ * O_ * 4]; // score partials
__device__ __align__(16) __half g_xjh[B_ * O_ * HH];   // x_j in fp16 (32MB)
__device__ __align__(16) __half g_UeH[HH * HH];        // U_e fp16
__device__ __align__(16) __half g_zh[B_ * 4096];       // [phi|X_F|h|c] fp16
__device__ __align__(16) float g_gp[4 * B_ * 4096];    // split-K=4 gate partials
__device__ int g_mflag;

// ---------------- helpers ----------------
__device__ __forceinline__ uint32_t smem_u32(const void* p) {
    uint32_t a;
    asm("{ .reg .u64 t; cvta.to.shared.u64 t, %1; cvt.u32.u64 %0, t; }" : "=r"(a) : "l"(p));
    return a;
}
__device__ __forceinline__ uint32_t swz(uint32_t off) { return off ^ ((off >> 3) & 0x70); }

__device__ __forceinline__ void ldsm4(uint32_t* r, uint32_t addr) {
    asm volatile("ldmatrix.sync.aligned.m8n8.x4.shared.b16 {%0,%1,%2,%3},[%4];"
        : "=r"(r[0]), "=r"(r[1]), "=r"(r[2]), "=r"(r[3]) : "r"(addr));
}
__device__ __forceinline__ void mma16816(float* c, const uint32_t* a, const uint32_t* b) {
    asm volatile("mma.sync.aligned.m16n8k16.row.col.f32.f16.f16.f32 "
        "{%0,%1,%2,%3},{%4,%5,%6,%7},{%8,%9},{%0,%1,%2,%3};"
        : "+f"(c[0]), "+f"(c[1]), "+f"(c[2]), "+f"(c[3])
        : "r"(a[0]), "r"(a[1]), "r"(a[2]), "r"(a[3]), "r"(b[0]), "r"(b[1]));
}
__device__ __forceinline__ void cp16(uint32_t dst, const void* src) {
    asm volatile("cp.async.cg.shared.global [%0],[%1],16;" :: "r"(dst), "l"(src));
}
#define CP_COMMIT() asm volatile("cp.async.commit_group;" ::: "memory")
#define CP_WAIT0()  asm volatile("cp.async.wait_group 0;" ::: "memory")

__device__ __forceinline__ uint32_t pk2(float a, float b) {
    __half2 x = __floats2half2_rn(a, b);
    uint32_t r; memcpy(&r, &x, 4); return r;
}
__device__ __forceinline__ float sigmoidf_(float x) { return 1.0f / (1.0f + expf(-x)); }

// fp16 (round-nearest) of a float4, stored swizzled as u64
__device__ __forceinline__ void cvt_f16h(char* hib, uint32_t off, float4 v) {
    uint32_t so = swz(off);
    uint32_t h0 = pk2(v.x, v.y);
    uint32_t h1 = pk2(v.z, v.w);
    *(u64*)(hib + so) = (u64)h0 | ((u64)h1 << 32);
}

// ---------------- kernel 0: sniff mask dtype ----------------
__global__ void k_sniff(const unsigned char* __restrict__ m) {
    __shared__ int anyBig, off123;
    if (threadIdx.x == 0) { anyBig = 0; off123 = 0; }
    __syncthreads();
    int big = 0, o123 = 0;
    for (int i = threadIdx.x; i < 4096; i += blockDim.x) {
        unsigned char v = m[i];
        if (v >= 2) big = 1;
        if ((i & 3) != 0 && v != 0) o123 = 1;
    }
    if (big) atomicOr(&anyBig, 1);
    if (o123) atomicOr(&off123, 1);
    __syncthreads();
    if (threadIdx.x == 0) g_mflag = anyBig ? 1 : (off123 ? 0 : 2);
}

// ---------------- conversion kernels ----------------
__global__ void k_cvt_xj(const float* __restrict__ xj) {
    size_t i = ((size_t)blockIdx.x * 256 + threadIdx.x) * 8;
    float4 v0 = *(const float4*)(xj + i);
    float4 v1 = *(const float4*)(xj + i + 4);
    uint4 o;
    o.x = pk2(v0.x, v0.y); o.y = pk2(v0.z, v0.w);
    o.z = pk2(v1.x, v1.y); o.w = pk2(v1.z, v1.w);
    *(uint4*)(g_xjh + i) = o;
}
__global__ void k_cvt_ue(const float* __restrict__ Ue) {
    size_t i = ((size_t)blockIdx.x * 256 + threadIdx.x) * 8;
    float4 v0 = *(const float4*)(Ue + i);
    float4 v1 = *(const float4*)(Ue + i + 4);
    uint4 hi;
    hi.x = pk2(v0.x, v0.y); hi.y = pk2(v0.z, v0.w);
    hi.z = pk2(v1.x, v1.y); hi.w = pk2(v1.z, v1.w);
    *(uint4*)(g_UeH + i) = hi;
}

// ---------------- kernel 1: g_hW partials = h @ W_e^T (split-K=8) ----------------
// grid (8, 4, 8): n-tile 64, m-tile 64, K slice 128. Slice 0 adds b_e.
__global__ void __launch_bounds__(256, 2)
k_hW(const float* __restrict__ h, const float* __restrict__ We,
     const float* __restrict__ be) {
    __shared__ __align__(16) float As[2][8][64];
    __shared__ __align__(16) float Bs[2][8][64];
    int t = threadIdx.x;
    int m0 = blockIdx.y * 64, n0 = blockIdx.x * 64;
    int ks = blockIdx.z;
    int tx = t & 15, ty = t >> 4;
    int lr = t >> 1, lp = (t & 1) * 4;
    const float* Ap = h  + (m0 + lr) * H_ + ks * 128 + lp;
    const float* Bp = We + (n0 + lr) * H_ + ks * 128 + lp;

    u64 acc[4][2] = {};
    float4 a4 = make_float4(0,0,0,0), b4 = make_float4(0,0,0,0);
    if (t < 128) { a4 = *(const float4*)Ap; b4 = *(const float4*)Bp; }
    if (t < 128) {
        As[0][lp+0][lr]=a4.x; As[0][lp+1][lr]=a4.y; As[0][lp+2][lr]=a4.z; As[0][lp+3][lr]=a4.w;
        Bs[0][lp+0][lr]=b4.x; Bs[0][lp+1][lr]=b4.y; Bs[0][lp+2][lr]=b4.z; Bs[0][lp+3][lr]=b4.w;
    }
    __syncthreads();
    int buf = 0;
    const int KT = 128 / 8;
    for (int kt = 0; kt < KT; kt++) {
        if (kt < KT - 1 && t < 128) {
            a4 = *(const float4*)(Ap + (kt + 1) * 8);
            b4 = *(const float4*)(Bp + (kt + 1) * 8);
        }
#pragma unroll
        for (int kk = 0; kk < 8; kk++) {
            float4 av = *(const float4*)&As[buf][kk][ty * 4];
            u64 b0 = *(const u64*)&Bs[buf][kk][tx * 4];
            u64 b1 = *(const u64*)&Bs[buf][kk][tx * 4 + 2];
            u64 ap;
            asm("mov.b64 %0,{%1,%1};" : "=l"(ap) : "f"(av.x));
            asm("fma.rn.f32x2 %0,%1,%2,%0;" : "+l"(acc[0][0]) : "l"(ap), "l"(b0));
            asm("fma.rn.f32x2 %0,%1,%2,%0;" : "+l"(acc[0][1]) : "l"(ap), "l"(b1));
            asm("mov.b64 %0,{%1,%1};" : "=l"(ap) : "f"(av.y));
            asm("fma.rn.f32x2 %0,%1,%2,%0;" : "+l"(acc[1][0]) : "l"(ap), "l"(b0));
            asm("fma.rn.f32x2 %0,%1,%2,%0;" : "+l"(acc[1][1]) : "l"(ap), "l"(b1));
            asm("mov.b64 %0,{%1,%1};" : "=l"(ap) : "f"(av.z));
            asm("fma.rn.f32x2 %0,%1,%2,%0;" : "+l"(acc[2][0]) : "l"(ap), "l"(b0));
            asm("fma.rn.f32x2 %0,%1,%2,%0;" : "+l"(acc[2][1]) : "l"(ap), "l"(b1));
            asm("mov.b64 %0,{%1,%1};" : "=l"(ap) : "f"(av.w));
            asm("fma.rn.f32x2 %0,%1,%2,%0;" : "+l"(acc[3][0]) : "l"(ap), "l"(b0));
            asm("fma.rn.f32x2 %0,%1,%2,%0;" : "+l"(acc[3][1]) : "l"(ap), "l"(b1));
        }
        if (kt < KT - 1) {
            int nb = buf ^ 1;
            if (t < 128) {
                As[nb][lp+0][lr]=a4.x; As[nb][lp+1][lr]=a4.y; As[nb][lp+2][lr]=a4.z; As[nb][lp+3][lr]=a4.w;
                Bs[nb][lp+0][lr]=b4.x; Bs[nb][lp+1][lr]=b4.y; Bs[nb][lp+2][lr]=b4.z; Bs[nb][lp+3][lr]=b4.w;
            }
            buf = nb;
        }
        __syncthreads();
    }
    float* outp = g_hW + (size_t)ks * B_ * HH;
#pragma unroll
    for (int i = 0; i < 4; i++) {
        int row = m0 + ty * 4 + i;
#pragma unroll
        for (int jp = 0; jp < 2; jp++) {
            float l, hv;
            asm("mov.b64 {%0,%1},%2;" : "=f"(l), "=f"(hv) : "l"(acc[i][jp]));
            int c0 = n0 + tx * 4 + jp * 2;
            float bb0 = (ks == 0) ? be[c0] : 0.f;
            float bb1 = (ks == 0) ? be[c0 + 1] : 0.f;
            outp[row * HH + c0]     = l  + bb0;
            outp[row * HH + c0 + 1] = hv + bb1;
        }
    }
}

// ================== mma core: single-term fp16 ==================
// buffer: A(0..16K) BH(16K..32K); BUFSZ_S=32K, double-buffered
#define B_HI  16384u
#define BUFSZ_S 32768u

__device__ __forceinline__ void mma_chunk1(float acc[2][8][4], uint32_t bb,
                                           int wm, int wn, int lane) {
#pragma unroll
    for (int ks = 0; ks < 4; ks++) {
        uint32_t bh[4][4];
        int mm = lane >> 3, ch = mm & 1;
        int rhalf = ((mm >> 1) << 3) + (lane & 7);
#pragma unroll
        for (int p = 0; p < 4; p++) {
            uint32_t off = (uint32_t)(wn * 64 + p * 16 + rhalf) * 128 + ks * 32 + ch * 16;
            ldsm4(bh[p], bb + B_HI + swz(off));
        }
#pragma unroll
        for (int mt = 0; mt < 2; mt++) {
            uint32_t offa = (uint32_t)(wm * 32 + mt * 16 + (lane & 15)) * 128
                          + ks * 32 + (lane >> 4) * 16;
            uint32_t ah[4];
            ldsm4(ah, bb + swz(offa));
#pragma unroll
            for (int nt = 0; nt < 8; nt++)
                mma16816(acc[mt][nt], ah, &bh[nt >> 1][(nt & 1) * 2]);
        }
    }
}

// ---------------- kernel 2: scores GEMM (single-term fp16, occ 2) ----------------
// grid (4, 256): nq = 128-col quarter of U_e, b = batch. M = 128 objects, K=512.
__global__ void __launch_bounds__(256, 2)
k_scores_mma(const float* __restrict__ w) {
    extern __shared__ __align__(1024) char smem[];
    uint32_t S = smem_u32(smem);
    const int t = threadIdx.x, wid = t >> 5, lane = t & 31;
    const int wm = wid >> 1, wn = wid & 1;
    const int nq = blockIdx.x, b = blockIdx.y;
    const int n0 = nq * 128;

    const uint32_t OFF_HW = 0, OFF_W = 512, OFF_RS = 1024, OFF_BUF = 2048;
    float* hWs = (float*)(smem + OFF_HW);
    float* ws  = (float*)(smem + OFF_W);
    float* rs  = (float*)(smem + OFF_RS);

    if (t < 128) {
        int idx = b * HH + n0 + t;
        float s8 = 0.f;
#pragma unroll
        for (int sk = 0; sk < 8; sk++) s8 += g_hW[(size_t)sk * B_ * HH + idx];
        hWs[t] = s8;
        ws[t] = w[n0 + t];
    }

    const int row_ = t >> 1;                  // 0..127 (thread pairs per row)
    const int c8a = (t & 1) * 4;              // base 16B-chunk within row half
    auto prefetch = [&](int kc, int buf) {
        uint32_t Sb = S + OFF_BUF + buf * BUFSZ_S;
        const __half* Asrc = g_xjh + (size_t)(b * O_ + row_) * HH + kc * 64;
        const __half* BHsrc = g_UeH + (size_t)(n0 + row_) * HH + kc * 64;
#pragma unroll
        for (int j = 0; j < 4; j++) {
            uint32_t off = swz((uint32_t)row_ * 128 + (c8a + j) * 16);
            cp16(Sb + off,        Asrc + (c8a + j) * 8);
            cp16(Sb + B_HI + off, BHsrc + (c8a + j) * 8);
        }
        CP_COMMIT();
    };

    float acc[2][8][4] = {};
    prefetch(0, 0);
    for (int c = 0; c < 8; c++) {
        CP_WAIT0();
        __syncthreads();
        if (c + 1 < 8) prefetch(c + 1, (c + 1) & 1);
        mma_chunk1(acc, S + OFF_BUF + (c & 1) * BUFSZ_S, wm, wn, lane);
    }

    // epilogue: tanh(C + hW) * w, reduce over 128 cols
    int g = lane >> 2, q = lane & 3;
#pragma unroll
    for (int mt = 0; mt < 2; mt++) {
        float sA = 0.f, sB = 0.f;
#pragma unroll
        for (int nt = 0; nt < 8; nt++) {
            int col = wn * 64 + nt * 8 + q * 2;
            sA += tanhf(acc[mt][nt][0] + hWs[col])     * ws[col];
            sA += tanhf(acc[mt][nt][1] + hWs[col + 1]) * ws[col + 1];
            sB += tanhf(acc[mt][nt][2] + hWs[col])     * ws[col];
            sB += tanhf(acc[mt][nt][3] + hWs[col + 1]) * ws[col + 1];
        }
        sA += __shfl_xor_sync(0xffffffffu, sA, 1);
        sA += __shfl_xor_sync(0xffffffffu, sA, 2);
        sB += __shfl_xor_sync(0xffffffffu, sB, 1);
        sB += __shfl_xor_sync(0xffffffffu, sB, 2);
        if (q == 0) {
            int r0 = wm * 32 + mt * 16 + g;
            rs[wn * 128 + r0]     = sA;
            rs[wn * 128 + r0 + 8] = sB;
        }
    }
    __syncthreads();
    if (t < 128)
        g_partial[(b * O_ + t) * 4 + nq] = rs[t] + rs[128 + t];
}

// ---------------- kernel 3: fused softmax + phi + z-gather (fp16 out) ----------------
__global__ void __launch_bounds__(512, 2)
k_attn_z(const void* __restrict__ mask, const float* __restrict__ XF,
         const float* __restrict__ h, const float* __restrict__ c) {
    __shared__ float sa[128], redm[128], reds[128], phis[512];
    int b = blockIdx.x, t = threadIdx.x;  // 512 threads
    float s = 0.f, e = 0.f;
    if (t < 128) {
        const float* pr = g_partial + (b * O_ + t) * 4;
        s = pr[0] + pr[1] + pr[2] + pr[3];
        int mf = g_mflag;
        bool mv;
        int mi = b * O_ + t;
        if (mf == 1)      mv = ((const float*)mask)[mi] != 0.0f;
        else if (mf == 2) mv = ((const int*)mask)[mi] != 0;
        else              mv = ((const unsigned char*)mask)[mi] != 0;
        if (!mv) s = -1e9f;
        redm[t] = s;
    }
    __syncthreads();
    for (int off = 64; off > 0; off >>= 1) {
        if (t < off) redm[t] = fmaxf(redm[t], redm[t + off]);
        __syncthreads();
    }
    float mx = redm[0];
    if (t < 128) { e = expf(s - mx); reds[t] = e; }
    __syncthreads();
    for (int off = 64; off > 0; off >>= 1) {
        if (t < off) reds[t] += reds[t + off];
        __syncthreads();
    }
    if (t < 128) sa[t] = e / reds[0];
    __syncthreads();

    // phi: thread t owns column t (512 cols), fp16 x_j
    float acc = 0.f;
    const __half* X = g_xjh + (size_t)b * O_ * HH;
    for (int o = 0; o < O_; o++)
        acc += sa[o] * __half2float(X[(size_t)o * HH + t]);
    phis[t] = acc;
    __syncthreads();

    // z fp16: 8 elems per thread
    int j0 = t * 8;
    float v[8];
    if (j0 < 512) {
#pragma unroll
        for (int k = 0; k < 8; k++) v[k] = phis[j0 + k];
    } else if (j0 < 2048) {
        const float* p = XF + (size_t)b * DFF + (j0 - 512);
        float4 a = *(const float4*)p, bq = *(const float4*)(p + 4);
        v[0]=a.x; v[1]=a.y; v[2]=a.z; v[3]=a.w; v[4]=bq.x; v[5]=bq.y; v[6]=bq.z; v[7]=bq.w;
    } else if (j0 < 3072) {
        const float* p = h + (size_t)b * H_ + (j0 - 2048);
        float4 a = *(const float4*)p, bq = *(const float4*)(p + 4);
        v[0]=a.x; v[1]=a.y; v[2]=a.z; v[3]=a.w; v[4]=bq.x; v[5]=bq.y; v[6]=bq.z; v[7]=bq.w;
    } else {
        const float* p = c + (size_t)b * H_ + (j0 - 3072);
        float4 a = *(const float4*)p, bq = *(const float4*)(p + 4);
        v[0]=a.x; v[1]=a.y; v[2]=a.z; v[3]=a.w; v[4]=bq.x; v[5]=bq.y; v[6]=bq.z; v[7]=bq.w;
    }
    uint4 o;
    o.x = pk2(v[0], v[1]); o.y = pk2(v[2], v[3]);
    o.z = pk2(v[4], v[5]); o.w = pk2(v[6], v[7]);
    *(uint4*)(g_zh + (size_t)b * 4096 + j0) = o;
}

// ---------------- kernel 4: gates GEMM (single-term fp16, split-K=4) ----------------
// grid (32, 2, 4): bx = n-block(128), by = m-block(128), bz = K slice (1024)
__global__ void __launch_bounds__(256, 1)
k_gates_mma(const float* __restrict__ Wi, const float* __restrict__ Wf,
            const float* __restrict__ Wc, const float* __restrict__ Wo,
            const float* __restrict__ Ui, const float* __restrict__ Uf,
            const float* __restrict__ Uc, const float* __restrict__ Uo,
            const float* __restrict__ Vi, const float* __restrict__ Vf,
            const float* __restrict__ Vo) {
    extern __shared__ __align__(1024) char smem[];
    uint32_t S = smem_u32(smem);
    const int t = threadIdx.x, wid = t >> 5, lane = t & 31;
    const int wm = wid >> 1, wn = wid & 1;
    const int nb_ = blockIdx.x, mb = blockIdx.y, ksp = blockIdx.z;
    const int n0g = nb_ * 128;
    const int gg = n0g >> 10;
    const int jb = n0g & 1023;
    const float* Wg = (gg == 0) ? Wi : (gg == 1) ? Wf : (gg == 2) ? Wc : Wo;
    const float* Ug = (gg == 0) ? Ui : (gg == 1) ? Uf : (gg == 2) ? Uc : Uo;
    const float* Vg = (gg == 0) ? Vi : (gg == 1) ? Vf : (gg == 3) ? Vo : nullptr;

    const int row_ = t >> 1;
    const int c8a = (t & 1) * 4;
    auto prefetchA = [&](int kc, int buf) {
        uint32_t Sb = S + buf * BUFSZ_S;
        const __half* Asrc = g_zh + (size_t)(mb * 128 + row_) * 4096
                           + ksp * 1024 + kc * 64;
#pragma unroll
        for (int j = 0; j < 4; j++) {
            uint32_t off = swz((uint32_t)row_ * 128 + (c8a + j) * 16);
            cp16(Sb + off, Asrc + (c8a + j) * 8);
        }
        CP_COMMIT();
    };

    float4 pb[8];
    auto loadB = [&](int kc) {
        int kk0 = ksp * 1024 + kc * 64;
        const float* bp = nullptr; int rstride = 0; bool zer = false;
        if (kk0 < 2048)      { bp = Wg + kk0;          rstride = 2048; }
        else if (kk0 < 3072) { bp = Ug + (kk0 - 2048); rstride = 1024; }
        else if (Vg)         { bp = Vg + (kk0 - 3072); rstride = 1024; }
        else                 { zer = true; }
#pragma unroll
        for (int i = 0; i < 8; i++) {
            int idx = i * 256 + t, row = idx >> 4, f4 = idx & 15;
            pb[i] = zer ? make_float4(0, 0, 0, 0)
                        : *(const float4*)(bp + (size_t)(jb + row) * rstride + f4 * 4);
        }
    };
    auto stsB = [&](int buf) {
        char* base = smem + buf * BUFSZ_S;
#pragma unroll
        for (int i = 0; i < 8; i++) {
            int idx = i * 256 + t, row = idx >> 4, f4 = idx & 15;
            cvt_f16h(base + B_HI, (uint32_t)row * 128 + f4 * 8, pb[i]);
        }
    };

    float acc[2][8][4] = {};
    loadB(0);
    stsB(0);
    prefetchA(0, 0);
    for (int c = 0; c < 16; c++) {
        CP_WAIT0();
        __syncthreads();
        if (c + 1 < 16) { loadB(c + 1); prefetchA(c + 1, (c + 1) & 1); }
        mma_chunk1(acc, S + (c & 1) * BUFSZ_S, wm, wn, lane);
        if (c + 1 < 16) stsB((c + 1) & 1);
    }

    // epilogue: store fp32 partials
    int g = lane >> 2, q = lane & 3;
#pragma unroll
    for (int mt = 0; mt < 2; mt++) {
        int m = mb * 128 + wm * 32 + mt * 16 + g;
        float* baseA = g_gp + (size_t)(ksp * B_ + m) * 4096 + n0g;
        float* baseB = g_gp + (size_t)(ksp * B_ + m + 8) * 4096 + n0g;
#pragma unroll
        for (int nt = 0; nt < 8; nt++) {
            int col = wn * 64 + nt * 8 + q * 2;
            *(float2*)(baseA + col) = make_float2(acc[mt][nt][0], acc[mt][nt][1]);
            *(float2*)(baseB + col) = make_float2(acc[mt][nt][2], acc[mt][nt][3]);
        }
    }
}

// ---------------- kernel 5: elementwise LSTM update ----------------
__global__ void k_final(const float* __restrict__ c,
                        const float* __restrict__ bi, const float* __restrict__ bf,
                        const float* __restrict__ bc, const float* __restrict__ bo,
                        float* __restrict__ out) {
    int idx = blockIdx.x * 256 + threadIdx.x;
    int b = idx >> 10, j = idx & 1023;
    const float* g0 = g_gp + (size_t)b * 4096;
    const float* g1 = g_gp + (size_t)(B_ + b) * 4096;
    const float* g2 = g_gp + (size_t)(2 * B_ + b) * 4096;
    const float* g3 = g_gp + (size_t)(3 * B_ + b) * 4096;
    float gi = g0[j]        + g1[j]        + g2[j]        + g3[j]        + bi[j];
    float gf = g0[1024 + j] + g1[1024 + j] + g2[1024 + j] + g3[1024 + j] + bf[j];
    float gc = g0[2048 + j] + g1[2048 + j] + g2[2048 + j] + g3[2048 + j] + bc[j];
    float go = g0[3072 + j] + g1[3072 + j] + g2[3072 + j] + g3[3072 + j] + bo[j];
    float si = sigmoidf_(gi);
    float sf = sigmoidf_(gf);
    float so = sigmoidf_(go);
    float cold = c[idx];
    float nc = sf * cold + si * tanhf(gc);
    float nh = so * tanhf(nc);
    out[idx] = nh;
    out[B_ * H_ + idx] = nc;
}

// ---------------- launch ----------------
extern "C" void kernel_launch(void* const* d_in, const int* in_sizes, int n_in,
                              void* d_out, int out_size) {
    const float* x_j  = (const float*)d_in[0];
    const void*  mask = d_in[1];
    const float* X_F  = (const float*)d_in[2];
    const float* h    = (const float*)d_in[3];
    const float* c    = (const float*)d_in[4];
    const float* W_i  = (const float*)d_in[5];
    const float* W_f  = (const float*)d_in[6];
    const float* W_c  = (const float*)d_in[7];
    const float* W_o  = (const float*)d_in[8];
    const float* U_i  = (const float*)d_in[9];
    const float* U_f  = (const float*)d_in[10];
    const float* U_c  = (const float*)d_in[11];
    const float* U_o  = (const float*)d_in[12];
    const float* V_i  = (const float*)d_in[13];
    const float* V_f  = (const float*)d_in[14];
    const float* V_o  = (const float*)d_in[16];
    const float* b_i  = (const float*)d_in[17];
    const float* b_f  = (const float*)d_in[18];
    const float* b_c  = (const float*)d_in[19];
    const float* b_o  = (const float*)d_in[20];
    const float* w    = (const float*)d_in[21];
    const float* W_e  = (const float*)d_in[22];
    const float* U_e  = (const float*)d_in[23];
    const float* b_e  = (const float*)d_in[24];

    cudaFuncSetAttribute(k_scores_mma, cudaFuncAttributeMaxDynamicSharedMemorySize, 67584);
    cudaFuncSetAttribute(k_gates_mma,  cudaFuncAttributeMaxDynamicSharedMemorySize, 65536);

    k_sniff<<<1, 256>>>((const unsigned char*)mask);
    k_cvt_xj<<<8192, 256>>>(x_j);
    k_cvt_ue<<<128, 256>>>(U_e);
    k_hW<<<dim3(8, 4, 8), 256>>>(h, W_e, b_e);
    k_scores_mma<<<dim3(4, 256), 256, 67584>>>(w);
    k_attn_z<<<256, 512>>>(mask, X_F, h, c);
    k_gates_mma<<<dim3(32, 2, 4), 256, 65536>>>(W_i, W_f, W_c, W_o,
                                                U_i, U_f, U_c, U_o,
                                                V_i, V_f, V_o);
    k_final<<<1024, 256>>>(c, b_i, b_f, b_c, b_o, (float*)d_out);
}